// round 6
// baseline (speedup 1.0000x reference)
#include <cuda_runtime.h>
#include <cuda_bf16.h>

#define NB 8
#define NL 1000
#define ND 512
#define NH 8
#define NDK 64
#define NR 1999   // 2*max_len - 1

// ---------------- device scratch (allocation-free rule) -----------------------
__device__ float g_xn[NB * NL * ND];
__device__ float g_q[NB * NH * NL * NDK];
__device__ float g_k[NB * NH * NL * NDK];
__device__ float g_v[NB * NH * NL * NDK];
__device__ float g_ctx[NB * NL * ND];

// ---------------- bf16 helpers ------------------------------------------------
// pack two f32 into one u32: low half = lo, high half = hi
__device__ __forceinline__ unsigned bf2(float lo, float hi) {
    unsigned r;
    asm("cvt.rn.bf16x2.f32 %0, %1, %2;" : "=r"(r) : "f"(hi), "f"(lo));
    return r;
}

// D(16x8,f32) += A(16x16,bf16,row) * B(16x8,bf16,col)
__device__ __forceinline__ void mma16(float4& d, uint4 a, uint2 b) {
    asm volatile(
        "mma.sync.aligned.m16n8k16.row.col.f32.bf16.bf16.f32 "
        "{%0,%1,%2,%3}, {%4,%5,%6,%7}, {%8,%9}, {%0,%1,%2,%3};\n"
        : "+f"(d.x), "+f"(d.y), "+f"(d.z), "+f"(d.w)
        : "r"(a.x), "r"(a.y), "r"(a.z), "r"(a.w), "r"(b.x), "r"(b.y));
}

// Fragment-permuted smem layouts, u32 (bf16x2 over k) units.
// A tile 16x16: elem (m,k): reg=((m>>3)&1)+((k>>3)&1)*2, lane=(m&7)*4+((k&7)>>1), half=k&1
__device__ __forceinline__ int a_off16(int m, int k, int nkt16) {
    return (((m >> 4) * nkt16 + (k >> 4)) << 7) +
           ((((m & 7) << 2) + ((k & 7) >> 1)) << 2) + ((m >> 3) & 1) + (((k >> 3) & 1) << 1);
}
// B tile 16x8: elem (k,n): reg=(k>>3)&1, lane=(n&7)*4+((k&7)>>1), half=k&1
__device__ __forceinline__ int b_off16(int k, int n, int nnt) {
    return (((k >> 4) * nnt + (n >> 3)) << 6) +
           ((((n & 7) << 2) + ((k & 7) >> 1)) << 1) + ((k >> 3) & 1);
}

// ---------------- LayerNorm ---------------------------------------------------
__global__ void ln_kernel(const float* __restrict__ x,
                          const float* __restrict__ gamma,
                          const float* __restrict__ beta) {
    int row = blockIdx.x;
    int tid = threadIdx.x;
    const float4 v = ((const float4*)(x + (size_t)row * ND))[tid];
    __shared__ float red[4];

    float s = v.x + v.y + v.z + v.w;
#pragma unroll
    for (int o = 16; o; o >>= 1) s += __shfl_xor_sync(0xffffffffu, s, o);
    if ((tid & 31) == 0) red[tid >> 5] = s;
    __syncthreads();
    float mean = (red[0] + red[1] + red[2] + red[3]) * (1.0f / ND);
    __syncthreads();

    float a = v.x - mean, b = v.y - mean, c = v.z - mean, d = v.w - mean;
    float s2 = a * a + b * b + c * c + d * d;
#pragma unroll
    for (int o = 16; o; o >>= 1) s2 += __shfl_xor_sync(0xffffffffu, s2, o);
    if ((tid & 31) == 0) red[tid >> 5] = s2;
    __syncthreads();
    float var = (red[0] + red[1] + red[2] + red[3]) * (1.0f / ND);
    float inv = rsqrtf(var + 1e-5f);

    const float4 gg = ((const float4*)gamma)[tid];
    const float4 bt = ((const float4*)beta)[tid];
    float4 o4;
    o4.x = a * inv * gg.x + bt.x;
    o4.y = b * inv * gg.y + bt.y;
    o4.z = c * inv * gg.z + bt.z;
    o4.w = d * inv * gg.w + bt.w;
    ((float4*)(g_xn + (size_t)row * ND))[tid] = o4;
}

// ---------------- bf16 tensor-core GEMM: C = A @ W^T + bias ------------------
// Block tile 64(M) x 128(N), k-step 32. 8 warps, warp tile 32x32.
__global__ void __launch_bounds__(256) gemm_kernel(
    const float* __restrict__ A, const float* __restrict__ W,
    const float* __restrict__ bias, const float* __restrict__ resid,
    float* __restrict__ C, int mode) {
    __shared__ unsigned As[1024];  // 64m x 32k bf16 (4 mt x 2 kt16 tiles)
    __shared__ unsigned Bs[2048];  // 32k x 128n bf16 (2 kt16 x 16 nt tiles)
    const int tid = threadIdx.x;
    const int lane = tid & 31, warp = tid >> 5;
    const int wm = warp >> 2, wn = warp & 3;
    const int g = lane >> 2, tig = lane & 3;
    const int m0 = blockIdx.y * 64, n0 = blockIdx.x * 128;
    float4 acc[2][4] = {};

    for (int k0 = 0; k0 < ND; k0 += 32) {
#pragma unroll
        for (int i = 0; i < 2; i++) {
            int f = tid + (i << 8);
            int m = f >> 3, kq = (f & 7) << 2;
            float4 v = *(const float4*)&A[(size_t)(m0 + m) * ND + k0 + kq];
            As[a_off16(m, kq, 2)] = bf2(v.x, v.y);
            As[a_off16(m, kq + 2, 2)] = bf2(v.z, v.w);
        }
#pragma unroll
        for (int i = 0; i < 4; i++) {
            int f = tid + (i << 8);
            int n = f >> 3, kq = (f & 7) << 2;
            float4 v = *(const float4*)&W[(size_t)(n0 + n) * ND + k0 + kq];
            Bs[b_off16(kq, n, 16)] = bf2(v.x, v.y);
            Bs[b_off16(kq + 2, n, 16)] = bf2(v.z, v.w);
        }
        __syncthreads();
#pragma unroll
        for (int kt = 0; kt < 2; kt++) {
            uint4 a0 = *(uint4*)&As[((((wm << 1) + 0) * 2 + kt) << 7) + (lane << 2)];
            uint4 a1 = *(uint4*)&As[((((wm << 1) + 1) * 2 + kt) << 7) + (lane << 2)];
            uint2 bf[4];
#pragma unroll
            for (int j = 0; j < 4; j++)
                bf[j] = *(uint2*)&Bs[((kt * 16 + (wn << 2) + j) << 6) + (lane << 1)];
#pragma unroll
            for (int j = 0; j < 4; j++) {
                mma16(acc[0][j], a0, bf[j]);
                mma16(acc[1][j], a1, bf[j]);
            }
        }
        __syncthreads();
    }

#pragma unroll
    for (int i = 0; i < 2; i++) {
#pragma unroll
        for (int j = 0; j < 4; j++) {
            int col = n0 + wn * 32 + j * 8 + (tig << 1);
            float2 bb = *(const float2*)&bias[col];
            float4 c = acc[i][j];
            int r0 = m0 + wm * 32 + i * 16 + g, r1 = r0 + 8;
            if (mode == 0) {
                int h = col >> 6, d = col & 63;
                int b0i = r0 / NL, l0 = r0 - b0i * NL;
                int b1i = r1 / NL, l1 = r1 - b1i * NL;
                *(float2*)&C[(((size_t)(b0i * NH + h) * NL + l0) << 6) + d] =
                    make_float2(c.x + bb.x, c.y + bb.y);
                *(float2*)&C[(((size_t)(b1i * NH + h) * NL + l1) << 6) + d] =
                    make_float2(c.z + bb.x, c.w + bb.y);
            } else {
                size_t o0 = (size_t)r0 * ND + col, o1 = (size_t)r1 * ND + col;
                float2 rr0 = *(const float2*)&resid[o0];
                float2 rr1 = *(const float2*)&resid[o1];
                *(float2*)&C[o0] = make_float2(c.x + bb.x + rr0.x, c.y + bb.y + rr0.y);
                *(float2*)&C[o1] = make_float2(c.z + bb.x + rr1.x, c.w + bb.y + rr1.y);
            }
        }
    }
}

// ---------------- bf16 tensor-core flash attention with rel-pos bias ---------
// Word offsets into dynamic smem (u32/f32 both 4B):
#define OFF_Q 0          // A-layout u32, 2048
#define OFF_K 2048       // B-layout k=d,n=j, u32 2048
#define OFF_V 4096       // B-layout k=j,n=d, u32 2048
#define OFF_P 6144       // A-layout u32 2048
#define OFF_R 8192       // B-layout k=d,n=band, nnt=16, u32 4096
#define OFF_S1 12288     // f32 [64][68]
#define OFF_S2 16640     // f32 [64][132]
#define OFF_M 25088
#define OFF_L 25152
#define OFF_A 25216
#define ATTN_SMEM_BYTES ((25216 + 64) * 4)

__global__ void __launch_bounds__(256) attn_kernel(const float* __restrict__ rel) {
    extern __shared__ float sm[];
    unsigned* Qs = (unsigned*)sm + OFF_Q;
    unsigned* Ks = (unsigned*)sm + OFF_K;
    unsigned* Vs = (unsigned*)sm + OFF_V;
    unsigned* Ps = (unsigned*)sm + OFF_P;
    unsigned* Rs = (unsigned*)sm + OFF_R;
    float* S1s = sm + OFF_S1;
    float* S2s = sm + OFF_S2;
    float* row_m = sm + OFF_M;
    float* row_l = sm + OFF_L;
    float* row_a = sm + OFF_A;

    const int it = blockIdx.x, bh = blockIdx.y;
    const int b = bh >> 3, h = bh & 7;
    const int i0 = it << 6;
    const int tid = threadIdx.x;
    const int lane = tid & 31, warp = tid >> 5;
    const int g = lane >> 2, tig = lane & 3;

    const float* qb = g_q + (size_t)bh * NL * NDK;
    const float* kb = g_k + (size_t)bh * NL * NDK;
    const float* vb = g_v + (size_t)bh * NL * NDK;

    // load Q tile into A-layout (zero OOB rows)
#pragma unroll
    for (int i = 0; i < 4; i++) {
        int f = tid + (i << 8);
        int r = f >> 4, c4 = (f & 15) << 2;
        float4 v = make_float4(0.f, 0.f, 0.f, 0.f);
        if (i0 + r < NL) v = *(const float4*)&qb[(size_t)(i0 + r) * NDK + c4];
        Qs[a_off16(r, c4, 4)] = bf2(v.x, v.y);
        Qs[a_off16(r, c4 + 2, 4)] = bf2(v.z, v.w);
    }
    if (tid < 64) { row_m[tid] = -1e30f; row_l[tid] = 0.f; }
    float4 O[4] = {};
    __syncthreads();

    for (int jt = 0; jt < 16; jt++) {
        const int j0 = jt << 6;
        // K (pre-scaled, B-layout k=d,n=j): pairs over d
#pragma unroll
        for (int i = 0; i < 4; i++) {
            int f = tid + (i << 8);
            int r = f >> 4, c4 = (f & 15) << 2;
            float4 kv = make_float4(0.f, 0.f, 0.f, 0.f);
            if (j0 + r < NL) kv = *(const float4*)&kb[(size_t)(j0 + r) * NDK + c4];
            Ks[b_off16(c4, r, 8)] = bf2(kv.x * 0.125f, kv.y * 0.125f);
            Ks[b_off16(c4 + 2, r, 8)] = bf2(kv.z * 0.125f, kv.w * 0.125f);
        }
        // V (B-layout k=j,n=d): pairs over j -> load two rows per thread
#pragma unroll
        for (int i = 0; i < 2; i++) {
            int f = tid + (i << 8);
            int rp = f >> 4, c4 = (f & 15) << 2;
            int je = j0 + (rp << 1);
            float4 ve = make_float4(0.f, 0.f, 0.f, 0.f);
            float4 vo = make_float4(0.f, 0.f, 0.f, 0.f);
            if (je < NL) ve = *(const float4*)&vb[(size_t)je * NDK + c4];
            if (je + 1 < NL) vo = *(const float4*)&vb[(size_t)(je + 1) * NDK + c4];
            Vs[b_off16(rp << 1, c4 + 0, 8)] = bf2(ve.x, vo.x);
            Vs[b_off16(rp << 1, c4 + 1, 8)] = bf2(ve.y, vo.y);
            Vs[b_off16(rp << 1, c4 + 2, 8)] = bf2(ve.z, vo.z);
            Vs[b_off16(rp << 1, c4 + 3, 8)] = bf2(ve.w, vo.w);
        }
        // rel band (128 rows) B-layout k=d,n=band: pairs over d
        const int rbase = j0 - i0 + (NL - 1) - 63;
#pragma unroll
        for (int i = 0; i < 8; i++) {
            int f = tid + (i << 8);
            int r = f >> 4, c4 = (f & 15) << 2;
            int rg = rbase + r;
            float4 v = make_float4(0.f, 0.f, 0.f, 0.f);
            if (rg >= 0 && rg < NR) v = *(const float4*)&rel[(size_t)rg * NDK + c4];
            Rs[b_off16(c4, r, 16)] = bf2(v.x, v.y);
            Rs[b_off16(c4 + 2, r, 16)] = bf2(v.z, v.w);
        }
        __syncthreads();

        // S1 = Q @ K^T : warp owns n8-tile `warp`
        {
            float4 s[4] = {};
#pragma unroll
            for (int kt = 0; kt < 4; kt++) {
                uint2 bfr = *(uint2*)&Ks[((kt * 8 + warp) << 6) + (lane << 1)];
#pragma unroll
                for (int mt = 0; mt < 4; mt++) {
                    uint4 afr = *(uint4*)&Qs[((mt * 4 + kt) << 7) + (lane << 2)];
                    mma16(s[mt], afr, bfr);
                }
            }
            int col = (warp << 3) + (tig << 1);
#pragma unroll
            for (int mt = 0; mt < 4; mt++) {
                int r0 = (mt << 4) + g;
                *(float2*)&S1s[r0 * 68 + col] = make_float2(s[mt].x, s[mt].y);
                *(float2*)&S1s[(r0 + 8) * 68 + col] = make_float2(s[mt].z, s[mt].w);
            }
        }
        // S2 = Q @ RelBand^T : warp owns n8-tiles {2w, 2w+1}
        {
            float4 s[4][2] = {};
#pragma unroll
            for (int kt = 0; kt < 4; kt++) {
                uint2 b0 = *(uint2*)&Rs[((kt * 16 + (warp << 1) + 0) << 6) + (lane << 1)];
                uint2 b1 = *(uint2*)&Rs[((kt * 16 + (warp << 1) + 1) << 6) + (lane << 1)];
#pragma unroll
                for (int mt = 0; mt < 4; mt++) {
                    uint4 afr = *(uint4*)&Qs[((mt * 4 + kt) << 7) + (lane << 2)];
                    mma16(s[mt][0], afr, b0);
                    mma16(s[mt][1], afr, b1);
                }
            }
#pragma unroll
            for (int mt = 0; mt < 4; mt++)
#pragma unroll
                for (int nl = 0; nl < 2; nl++) {
                    int col = (((warp << 1) + nl) << 3) + (tig << 1);
                    int r0 = (mt << 4) + g;
                    *(float2*)&S2s[r0 * 132 + col] = make_float2(s[mt][nl].x, s[mt][nl].y);
                    *(float2*)&S2s[(r0 + 8) * 132 + col] = make_float2(s[mt][nl].z, s[mt][nl].w);
                }
        }
        __syncthreads();

        // online softmax with rel gather: S[i][c] = S1[i][c] + S2[i][c-i+63]
        {
            int i = tid >> 2, q = tid & 3;
            int cbase = q << 4;
            float e[16];
            float mx = -1e30f;
#pragma unroll
            for (int c = 0; c < 16; c++) {
                int cc = cbase + c;
                float s = S1s[i * 68 + cc] + S2s[i * 132 + cc - i + 63];
                e[c] = (j0 + cc >= NL) ? -1e30f : s;
                mx = fmaxf(mx, e[c]);
            }
            mx = fmaxf(mx, __shfl_xor_sync(0xffffffffu, mx, 1));
            mx = fmaxf(mx, __shfl_xor_sync(0xffffffffu, mx, 2));
            float mold = row_m[i];
            float mnew = fmaxf(mold, mx);
            float alpha = __expf(mold - mnew);
            float ssum = 0.f;
#pragma unroll
            for (int c = 0; c < 16; c++) {
                float ev = __expf(e[c] - mnew);
                e[c] = ev;
                ssum += ev;
            }
#pragma unroll
            for (int p = 0; p < 8; p++)
                Ps[a_off16(i, cbase + (p << 1), 4)] = bf2(e[p << 1], e[(p << 1) + 1]);
            ssum += __shfl_xor_sync(0xffffffffu, ssum, 1);
            ssum += __shfl_xor_sync(0xffffffffu, ssum, 2);
            if (q == 0) {
                row_m[i] = mnew;
                row_a[i] = alpha;
                row_l[i] = row_l[i] * alpha + ssum;
            }
        }
        __syncthreads();

        // rescale O then O += P @ V (warp owns n8-tile `warp` of dk)
        {
#pragma unroll
            for (int mt = 0; mt < 4; mt++) {
                float a0 = row_a[(mt << 4) + g];
                float a1 = row_a[(mt << 4) + 8 + g];
                O[mt].x *= a0; O[mt].y *= a0;
                O[mt].z *= a1; O[mt].w *= a1;
            }
#pragma unroll
            for (int kt = 0; kt < 4; kt++) {
                uint2 bfr = *(uint2*)&Vs[((kt * 8 + warp) << 6) + (lane << 1)];
#pragma unroll
                for (int mt = 0; mt < 4; mt++) {
                    uint4 afr = *(uint4*)&Ps[((mt * 4 + kt) << 7) + (lane << 2)];
                    mma16(O[mt], afr, bfr);
                }
            }
        }
        __syncthreads();
    }

    // normalize + write ctx into (B, L, D)
#pragma unroll
    for (int mt = 0; mt < 4; mt++) {
        int r0 = (mt << 4) + g, r1 = r0 + 8;
        int col = (warp << 3) + (tig << 1);
        if (i0 + r0 < NL) {
            float inv = 1.f / row_l[r0];
            *(float2*)&g_ctx[((size_t)(b * NL + i0 + r0)) * ND + (h << 6) + col] =
                make_float2(O[mt].x * inv, O[mt].y * inv);
        }
        if (i0 + r1 < NL) {
            float inv = 1.f / row_l[r1];
            *(float2*)&g_ctx[((size_t)(b * NL + i0 + r1)) * ND + (h << 6) + col] =
                make_float2(O[mt].z * inv, O[mt].w * inv);
        }
    }
}

// ---------------- launch ------------------------------------------------------
extern "C" void kernel_launch(void* const* d_in, const int* in_sizes, int n_in,
                              void* d_out, int out_size) {
    const float* x     = (const float*)d_in[0];
    const float* Wq    = (const float*)d_in[1];
    const float* bq    = (const float*)d_in[2];
    const float* Wk    = (const float*)d_in[3];
    const float* bk    = (const float*)d_in[4];
    const float* Wv    = (const float*)d_in[5];
    const float* bv    = (const float*)d_in[6];
    const float* Wo    = (const float*)d_in[7];
    const float* bo    = (const float*)d_in[8];
    const float* rel   = (const float*)d_in[9];
    const float* gamma = (const float*)d_in[10];
    const float* beta  = (const float*)d_in[11];
    float* out = (float*)d_out;

    void *pxn = nullptr, *pq = nullptr, *pk = nullptr, *pv = nullptr, *pctx = nullptr;
    cudaGetSymbolAddress(&pxn, g_xn);
    cudaGetSymbolAddress(&pq, g_q);
    cudaGetSymbolAddress(&pk, g_k);
    cudaGetSymbolAddress(&pv, g_v);
    cudaGetSymbolAddress(&pctx, g_ctx);

    cudaFuncSetAttribute(attn_kernel, cudaFuncAttributeMaxDynamicSharedMemorySize,
                         ATTN_SMEM_BYTES);

    ln_kernel<<<NB * NL, 128>>>(x, gamma, beta);

    dim3 gg(ND / 128, (NB * NL) / 64);  // (4, 125)
    gemm_kernel<<<gg, 256>>>((const float*)pxn, Wq, bq, nullptr, (float*)pq, 0);
    gemm_kernel<<<gg, 256>>>((const float*)pxn, Wk, bk, nullptr, (float*)pk, 0);
    gemm_kernel<<<gg, 256>>>((const float*)pxn, Wv, bv, nullptr, (float*)pv, 0);

    attn_kernel<<<dim3(16, NB * NH), 256, ATTN_SMEM_BYTES>>>(rel);

    gemm_kernel<<<gg, 256>>>((const float*)pctx, Wo, bo, x, out, 1);
}

// round 7
// speedup vs baseline: 1.2522x; 1.2522x over previous
#include <cuda_runtime.h>
#include <cuda_bf16.h>

#define NL 1000
#define ND 512
#define NH 8
#define NDK 64
#define NRR 1999
#define NBH 64

// ---------------- device scratch: pre-permuted bf16 fragment arrays -----------
__device__ unsigned g_xnp [500 * 32 * 128];   // xn  A-perm (8000 x 512)
__device__ unsigned g_ctxp[500 * 32 * 128];   // ctx A-perm (8000 x 512)
__device__ unsigned g_wp  [4 * 131072];       // W   B-perm (512k x 512n) x4
__device__ unsigned g_qp  [NBH * 32768];      // q per bh: A-perm (1024 x 64)
__device__ unsigned g_kp  [NBH * 32768];      // k per bh: B-perm k=d(64), n=j(1024)
__device__ unsigned g_vrow[NBH * 32768];      // v per bh: row-major bf16 (1024 x 64)
__device__ unsigned g_relp[4 * 272 * 64];     // rel B-perm k=d(64), n=u+64 (2176 pad)

// ---------------- helpers -----------------------------------------------------
__device__ __forceinline__ unsigned bf2(float lo, float hi) {
    unsigned r;
    asm("cvt.rn.bf16x2.f32 %0, %1, %2;" : "=r"(r) : "f"(hi), "f"(lo));
    return r;
}
__device__ __forceinline__ unsigned prmt(unsigned a, unsigned b, unsigned sel) {
    unsigned r;
    asm("prmt.b32 %0, %1, %2, %3;" : "=r"(r) : "r"(a), "r"(b), "r"(sel));
    return r;
}
__device__ __forceinline__ void mma16(float4& d, uint4 a, uint2 b) {
    asm volatile(
        "mma.sync.aligned.m16n8k16.row.col.f32.bf16.bf16.f32 "
        "{%0,%1,%2,%3}, {%4,%5,%6,%7}, {%8,%9}, {%0,%1,%2,%3};\n"
        : "+f"(d.x), "+f"(d.y), "+f"(d.z), "+f"(d.w)
        : "r"(a.x), "r"(a.y), "r"(a.z), "r"(a.w), "r"(b.x), "r"(b.y));
}
// A tile 16x16 (u32 = bf16x2 over k)
__device__ __forceinline__ int a_off16(int m, int k, int nkt16) {
    return (((m >> 4) * nkt16 + (k >> 4)) << 7) +
           ((((m & 7) << 2) + ((k & 7) >> 1)) << 2) + ((m >> 3) & 1) + (((k >> 3) & 1) << 1);
}
// B tile 16x8 (u32 = bf16x2 over k)
__device__ __forceinline__ int b_off16(int k, int n, int nnt) {
    return (((k >> 4) * nnt + (n >> 3)) << 6) +
           ((((n & 7) << 2) + ((k & 7) >> 1)) << 1) + ((k >> 3) & 1);
}

// ---------------- zero the padding rows (1000..1023) of qp/kp/vrow ------------
__global__ void zfill_kernel() {
    int bh = blockIdx.x;
    int t = threadIdx.x;                     // 768 items: 24 rows x 32 k-pairs
    for (int f = t; f < 768; f += 256) {
        int m = 1000 + (f >> 5);
        int k = (f & 31) << 1;
        g_qp[bh * 32768 + a_off16(m, k, 4)] = 0;
        g_kp[bh * 32768 + b_off16(k, m, 128)] = 0;
        g_vrow[bh * 32768 + m * 32 + (f & 31)] = 0;
    }
}

// ---------------- LayerNorm -> A-perm bf16 ------------------------------------
__global__ void ln_kernel(const float* __restrict__ x,
                          const float* __restrict__ gamma,
                          const float* __restrict__ beta) {
    int row = blockIdx.x;
    int tid = threadIdx.x;
    const float4 v = ((const float4*)(x + (size_t)row * ND))[tid];
    __shared__ float red[4];

    float s = v.x + v.y + v.z + v.w;
#pragma unroll
    for (int o = 16; o; o >>= 1) s += __shfl_xor_sync(0xffffffffu, s, o);
    if ((tid & 31) == 0) red[tid >> 5] = s;
    __syncthreads();
    float mean = (red[0] + red[1] + red[2] + red[3]) * (1.0f / ND);
    __syncthreads();

    float a = v.x - mean, b = v.y - mean, c = v.z - mean, d = v.w - mean;
    float s2 = a * a + b * b + c * c + d * d;
#pragma unroll
    for (int o = 16; o; o >>= 1) s2 += __shfl_xor_sync(0xffffffffu, s2, o);
    if ((tid & 31) == 0) red[tid >> 5] = s2;
    __syncthreads();
    float var = (red[0] + red[1] + red[2] + red[3]) * (1.0f / ND);
    float inv = rsqrtf(var + 1e-5f);

    const float4 gg = ((const float4*)gamma)[tid];
    const float4 bt = ((const float4*)beta)[tid];
    float o0 = a * inv * gg.x + bt.x;
    float o1 = b * inv * gg.y + bt.y;
    float o2 = c * inv * gg.z + bt.z;
    float o3 = d * inv * gg.w + bt.w;
    int k0 = tid << 2;
    g_xnp[a_off16(row, k0, 32)] = bf2(o0, o1);
    g_xnp[a_off16(row, k0 + 2, 32)] = bf2(o2, o3);
}

// ---------------- weight -> B-perm bf16 ---------------------------------------
__global__ void wconv_kernel(const float* __restrict__ W, int widx) {
    int idx = blockIdx.x * 256 + threadIdx.x;   // 131072 words
    int n = idx >> 8, k = (idx & 255) << 1;
    g_wp[widx * 131072 + b_off16(k, n, 64)] =
        bf2(W[(size_t)n * ND + k], W[(size_t)n * ND + k + 1]);
}

// ---------------- rel -> B-perm bf16 (n index = u_abs + 64, zero pad) ---------
__global__ void relconv_kernel(const float* __restrict__ rel) {
    int idx = blockIdx.x * 256 + threadIdx.x;   // 69632 words
    int u = idx >> 5, k = (idx & 31) << 1;
    int ua = u - 64;
    float a = 0.f, b = 0.f;
    if (ua >= 0 && ua < NRR) {
        a = rel[(size_t)ua * NDK + k];
        b = rel[(size_t)ua * NDK + k + 1];
    }
    g_relp[b_off16(k, u, 272)] = bf2(a, b);
}

// ---------------- streaming bf16 GEMM (no smem, no syncs) ---------------------
// A: 8000x512 A-perm (g_xnp or g_ctxp), B: g_wp[widx]. Block 64m x 128n.
// mode 0: ->g_qp  2: ->g_kp (x0.125)  3: ->g_vrow  1: f32 C + bias + resid
__global__ void __launch_bounds__(256) gemm2_kernel(
    const float* __restrict__ bias, const float* __restrict__ resid,
    float* __restrict__ Cf, int mode, int widx) {
    const int tid = threadIdx.x, lane = tid & 31, warp = tid >> 5;
    const int wm = warp >> 2, wn = warp & 3, g = lane >> 2, tig = lane & 3;
    const int m0 = blockIdx.y * 64, n0 = blockIdx.x * 128;
    const unsigned* Ap = (mode == 1) ? g_ctxp : g_xnp;
    const unsigned* Ab = Ap + (size_t)(((m0 + wm * 32) >> 4) * 32) * 128 + (lane << 2);
    const unsigned* Bb = g_wp + (size_t)widx * 131072 + (size_t)((n0 >> 3) + wn * 4) * 64 + (lane << 1);

    float4 acc[2][4] = {};
    uint4 a[2][2];
    uint2 b[2][4];
    a[0][0] = *(const uint4*)(Ab);
    a[0][1] = *(const uint4*)(Ab + 4096);
#pragma unroll
    for (int j = 0; j < 4; j++) b[0][j] = *(const uint2*)(Bb + j * 64);
#pragma unroll
    for (int kt = 0; kt < 32; kt++) {
        int cur = kt & 1, nxt = cur ^ 1;
        if (kt < 31) {
            a[nxt][0] = *(const uint4*)(Ab + (kt + 1) * 128);
            a[nxt][1] = *(const uint4*)(Ab + 4096 + (kt + 1) * 128);
#pragma unroll
            for (int j = 0; j < 4; j++)
                b[nxt][j] = *(const uint2*)(Bb + (size_t)(kt + 1) * 4096 + j * 64);
        }
#pragma unroll
        for (int j = 0; j < 4; j++) {
            mma16(acc[0][j], a[cur][0], b[cur][j]);
            mma16(acc[1][j], a[cur][1], b[cur][j]);
        }
    }

#pragma unroll
    for (int i = 0; i < 2; i++)
#pragma unroll
        for (int j = 0; j < 4; j++) {
            int col = n0 + wn * 32 + j * 8 + (tig << 1);
            float2 bb = *(const float2*)&bias[col];
            float4 c = acc[i][j];
            float cx = c.x + bb.x, cy = c.y + bb.y;
            float cz = c.z + bb.x, cw = c.w + bb.y;
            int r0 = m0 + wm * 32 + i * 16 + g, r1 = r0 + 8;
            if (mode == 1) {
                size_t o0 = (size_t)r0 * ND + col, o1 = (size_t)r1 * ND + col;
                float2 rr0 = *(const float2*)&resid[o0];
                float2 rr1 = *(const float2*)&resid[o1];
                *(float2*)&Cf[o0] = make_float2(cx + rr0.x, cy + rr0.y);
                *(float2*)&Cf[o1] = make_float2(cz + rr1.x, cw + rr1.y);
            } else {
                int h = col >> 6, d = col & 63;
                int b0i = r0 / NL, l0 = r0 - b0i * NL;
                int b1i = r1 / NL, l1 = r1 - b1i * NL;
                int bh0 = b0i * NH + h, bh1 = b1i * NH + h;
                if (mode == 0) {
                    g_qp[bh0 * 32768 + a_off16(l0, d, 4)] = bf2(cx, cy);
                    g_qp[bh1 * 32768 + a_off16(l1, d, 4)] = bf2(cz, cw);
                } else if (mode == 2) {
                    g_kp[bh0 * 32768 + b_off16(d, l0, 128)] = bf2(cx * 0.125f, cy * 0.125f);
                    g_kp[bh1 * 32768 + b_off16(d, l1, 128)] = bf2(cz * 0.125f, cw * 0.125f);
                } else {
                    g_vrow[bh0 * 32768 + l0 * 32 + (d >> 1)] = bf2(cx, cy);
                    g_vrow[bh1 * 32768 + l1 * 32 + (d >> 1)] = bf2(cz, cw);
                }
            }
        }
}

// ---------------- flash attention: fragments direct from permuted global ------
// smem (u32 words): V double buffer 2x2048 | P 2048 | S1 64x68 f32 | S2 64x132 | m/l/a
#define OFF_V 0
#define OFF_P 4096
#define OFF_S1 6144
#define OFF_S2 10496
#define OFF_M 18944
#define OFF_L 19008
#define OFF_A 19072
#define ATTN_WORDS (19072 + 64)
#define ATTN_SMEM_BYTES (ATTN_WORDS * 4)

__global__ void __launch_bounds__(256) attn_kernel() {
    extern __shared__ float sm[];
    unsigned* Vs = (unsigned*)sm + OFF_V;
    unsigned* Ps = (unsigned*)sm + OFF_P;
    float* S1s = sm + OFF_S1;
    float* S2s = sm + OFF_S2;
    float* row_m = sm + OFF_M;
    float* row_l = sm + OFF_L;
    float* row_a = sm + OFF_A;

    const int it = blockIdx.x, bh = blockIdx.y;
    const int bq = bh >> 3, h = bh & 7;
    const int i0 = it << 6;
    const int tid = threadIdx.x;
    const int lane = tid & 31, warp = tid >> 5;
    const int g = lane >> 2, tig = lane & 3;

    const unsigned* qpb = g_qp + bh * 32768;
    const unsigned* kpb = g_kp + bh * 32768;
    const unsigned* vrb = g_vrow + bh * 32768;

    if (tid < 64) { row_m[tid] = -1e30f; row_l[tid] = 0.f; }
    float4 O[4] = {};
    __syncthreads();

    for (int jt = 0; jt < 16; jt++) {
        const int j0 = jt << 6;
        unsigned* Vbuf = Vs + ((jt & 1) << 11);

        // stage V tile: row-major bf16 -> B-perm (pair over j via prmt)
#pragma unroll
        for (int i = 0; i < 4; i++) {
            int f = tid + (i << 8);
            int rp = f >> 5, c2 = f & 31;          // rp: j-pair 0..31, c2: d-pair 0..31
            unsigned wa = vrb[(j0 + (rp << 1)) * 32 + c2];
            unsigned wb = vrb[(j0 + (rp << 1) + 1) * 32 + c2];
            Vbuf[b_off16(rp << 1, c2 << 1, 8)] = prmt(wa, wb, 0x5410);
            Vbuf[b_off16(rp << 1, (c2 << 1) + 1, 8)] = prmt(wa, wb, 0x7632);
        }

        // S1 = Q @ K^T : warp owns j-n8-tile `warp`; frags straight from global
        {
            float4 s[4] = {};
#pragma unroll
            for (int kt = 0; kt < 4; kt++) {
                uint2 bfr = *(const uint2*)(kpb + (size_t)(kt * 128 + (jt << 3) + warp) * 64 + (lane << 1));
#pragma unroll
                for (int mt = 0; mt < 4; mt++) {
                    uint4 afr = *(const uint4*)(qpb + (size_t)(((it << 2) + mt) * 4 + kt) * 128 + (lane << 2));
                    mma16(s[mt], afr, bfr);
                }
            }
            int col = (warp << 3) + (tig << 1);
#pragma unroll
            for (int mt = 0; mt < 4; mt++) {
                int r0 = (mt << 4) + g;
                *(float2*)&S1s[r0 * 68 + col] = make_float2(s[mt].x, s[mt].y);
                *(float2*)&S1s[(r0 + 8) * 68 + col] = make_float2(s[mt].z, s[mt].w);
            }
        }
        // S2 = Q @ RelBand^T : band n-base = j0-i0+1000; warp owns tiles {2w,2w+1}
        {
            const int ntb = ((j0 - i0 + 1000) >> 3);
            float4 s[4][2] = {};
#pragma unroll
            for (int kt = 0; kt < 4; kt++) {
                uint2 b0 = *(const uint2*)(g_relp + (size_t)(kt * 272 + ntb + (warp << 1)) * 64 + (lane << 1));
                uint2 b1 = *(const uint2*)(g_relp + (size_t)(kt * 272 + ntb + (warp << 1) + 1) * 64 + (lane << 1));
#pragma unroll
                for (int mt = 0; mt < 4; mt++) {
                    uint4 afr = *(const uint4*)(qpb + (size_t)(((it << 2) + mt) * 4 + kt) * 128 + (lane << 2));
                    mma16(s[mt][0], afr, b0);
                    mma16(s[mt][1], afr, b1);
                }
            }
#pragma unroll
            for (int mt = 0; mt < 4; mt++)
#pragma unroll
                for (int nl = 0; nl < 2; nl++) {
                    int col = (((warp << 1) + nl) << 3) + (tig << 1);
                    int r0 = (mt << 4) + g;
                    *(float2*)&S2s[r0 * 132 + col] = make_float2(s[mt][nl].x, s[mt][nl].y);
                    *(float2*)&S2s[(r0 + 8) * 132 + col] = make_float2(s[mt][nl].z, s[mt][nl].w);
                }
        }
        __syncthreads();

        // online softmax with band gather: S[i][c] = S1[i][c] + S2[i][c-i+63]
        {
            int i = tid >> 2, q = tid & 3;
            int cbase = q << 4;
            float e[16];
            float mx = -1e30f;
#pragma unroll
            for (int c = 0; c < 16; c++) {
                int cc = cbase + c;
                float s = S1s[i * 68 + cc] + S2s[i * 132 + cc - i + 63];
                e[c] = (j0 + cc >= NL) ? -1e30f : s;
                mx = fmaxf(mx, e[c]);
            }
            mx = fmaxf(mx, __shfl_xor_sync(0xffffffffu, mx, 1));
            mx = fmaxf(mx, __shfl_xor_sync(0xffffffffu, mx, 2));
            float mold = row_m[i];
            float mnew = fmaxf(mold, mx);
            float alpha = __expf(mold - mnew);
            float ssum = 0.f;
#pragma unroll
            for (int c = 0; c < 16; c++) {
                float ev = __expf(e[c] - mnew);
                e[c] = ev;
                ssum += ev;
            }
#pragma unroll
            for (int p = 0; p < 8; p++)
                Ps[a_off16(i, cbase + (p << 1), 4)] = bf2(e[p << 1], e[(p << 1) + 1]);
            ssum += __shfl_xor_sync(0xffffffffu, ssum, 1);
            ssum += __shfl_xor_sync(0xffffffffu, ssum, 2);
            if (q == 0) {
                row_m[i] = mnew;
                row_a[i] = alpha;
                row_l[i] = row_l[i] * alpha + ssum;
            }
        }
        __syncthreads();

        // rescale O, then O += P @ V (warp owns d-n8-tile `warp`)
        {
#pragma unroll
            for (int mt = 0; mt < 4; mt++) {
                float a0 = row_a[(mt << 4) + g];
                float a1 = row_a[(mt << 4) + 8 + g];
                O[mt].x *= a0; O[mt].y *= a0;
                O[mt].z *= a1; O[mt].w *= a1;
            }
#pragma unroll
            for (int kt = 0; kt < 4; kt++) {
                uint2 bfr = *(uint2*)&Vbuf[((kt * 8 + warp) << 6) + (lane << 1)];
#pragma unroll
                for (int mt = 0; mt < 4; mt++) {
                    uint4 afr = *(uint4*)&Ps[((mt * 4 + kt) << 7) + (lane << 2)];
                    mma16(O[mt], afr, bfr);
                }
            }
        }
    }

    // normalize + write ctx as A-perm bf16 (global row = bq*1000 + i)
#pragma unroll
    for (int mt = 0; mt < 4; mt++) {
        int r0 = (mt << 4) + g, r1 = r0 + 8;
        int col = (warp << 3) + (tig << 1);
        if (i0 + r0 < NL) {
            float inv = 1.f / row_l[r0];
            int gm = bq * NL + i0 + r0;
            g_ctxp[a_off16(gm, (h << 6) + col, 32)] = bf2(O[mt].x * inv, O[mt].y * inv);
        }
        if (i0 + r1 < NL) {
            float inv = 1.f / row_l[r1];
            int gm = bq * NL + i0 + r1;
            g_ctxp[a_off16(gm, (h << 6) + col, 32)] = bf2(O[mt].z * inv, O[mt].w * inv);
        }
    }
}

// ---------------- launch ------------------------------------------------------
extern "C" void kernel_launch(void* const* d_in, const int* in_sizes, int n_in,
                              void* d_out, int out_size) {
    const float* x     = (const float*)d_in[0];
    const float* Wq    = (const float*)d_in[1];
    const float* bq    = (const float*)d_in[2];
    const float* Wk    = (const float*)d_in[3];
    const float* bk    = (const float*)d_in[4];
    const float* Wv    = (const float*)d_in[5];
    const float* bv    = (const float*)d_in[6];
    const float* Wo    = (const float*)d_in[7];
    const float* bo    = (const float*)d_in[8];
    const float* rel   = (const float*)d_in[9];
    const float* gamma = (const float*)d_in[10];
    const float* beta  = (const float*)d_in[11];
    float* out = (float*)d_out;

    cudaFuncSetAttribute(attn_kernel, cudaFuncAttributeMaxDynamicSharedMemorySize,
                         ATTN_SMEM_BYTES);

    zfill_kernel<<<NBH, 256>>>();
    ln_kernel<<<8 * NL, 128>>>(x, gamma, beta);
    wconv_kernel<<<512, 256>>>(Wq, 0);
    wconv_kernel<<<512, 256>>>(Wk, 1);
    wconv_kernel<<<512, 256>>>(Wv, 2);
    wconv_kernel<<<512, 256>>>(Wo, 3);
    relconv_kernel<<<272, 256>>>(rel);

    dim3 gg(4, 125);
    gemm2_kernel<<<gg, 256>>>(bq, nullptr, nullptr, 0, 0);   // Q
    gemm2_kernel<<<gg, 256>>>(bk, nullptr, nullptr, 2, 1);   // K (scaled)
    gemm2_kernel<<<gg, 256>>>(bv, nullptr, nullptr, 3, 2);   // V

    attn_kernel<<<dim3(16, NBH), 256, ATTN_SMEM_BYTES>>>();

    gemm2_kernel<<<gg, 256>>>(bo, x, out, 1, 3);             // out-proj + residual
}

// round 8
// speedup vs baseline: 1.5048x; 1.2017x over previous
#include <cuda_runtime.h>
#include <cuda_bf16.h>

#define NL 1000
#define ND 512
#define NH 8
#define NDK 64
#define NRR 1999
#define NBH 64
#define LOG2E 1.4426950408889634f

// ---------------- device scratch: pre-permuted bf16 fragment arrays -----------
__device__ unsigned g_xnp [500 * 32 * 128];   // xn  A-perm (8000 x 512)
__device__ unsigned g_ctxp[500 * 32 * 128];   // ctx A-perm (8000 x 512)
__device__ unsigned g_wp  [4 * 131072];       // W   B-perm (512k x 512n) x4
__device__ unsigned g_qp  [NBH * 32768];      // q per bh: A-perm (1024 x 64)
__device__ unsigned g_kp  [NBH * 32768];      // k per bh: B-perm k=d, n=j (x0.125*log2e)
__device__ unsigned g_vrow[NBH * 32768];      // v per bh: row-major bf16 (1024 x 64)
__device__ unsigned g_relp[4 * 272 * 64];     // rel*log2e B-perm k=d, n=u_abs+64

// ---------------- helpers -----------------------------------------------------
__device__ __forceinline__ unsigned bf2(float lo, float hi) {
    unsigned r;
    asm("cvt.rn.bf16x2.f32 %0, %1, %2;" : "=r"(r) : "f"(hi), "f"(lo));
    return r;
}
__device__ __forceinline__ unsigned prmt(unsigned a, unsigned b, unsigned sel) {
    unsigned r;
    asm("prmt.b32 %0, %1, %2, %3;" : "=r"(r) : "r"(a), "r"(b), "r"(sel));
    return r;
}
__device__ __forceinline__ float ex2f(float x) {
    float r;
    asm("ex2.approx.ftz.f32 %0, %1;" : "=f"(r) : "f"(x));
    return r;
}
__device__ __forceinline__ void mma16(float4& d, uint4 a, uint2 b) {
    asm volatile(
        "mma.sync.aligned.m16n8k16.row.col.f32.bf16.bf16.f32 "
        "{%0,%1,%2,%3}, {%4,%5,%6,%7}, {%8,%9}, {%0,%1,%2,%3};\n"
        : "+f"(d.x), "+f"(d.y), "+f"(d.z), "+f"(d.w)
        : "r"(a.x), "r"(a.y), "r"(a.z), "r"(a.w), "r"(b.x), "r"(b.y));
}
__device__ __forceinline__ int a_off16(int m, int k, int nkt16) {
    return (((m >> 4) * nkt16 + (k >> 4)) << 7) +
           ((((m & 7) << 2) + ((k & 7) >> 1)) << 2) + ((m >> 3) & 1) + (((k >> 3) & 1) << 1);
}
__device__ __forceinline__ int b_off16(int k, int n, int nnt) {
    return (((k >> 4) * nnt + (n >> 3)) << 6) +
           ((((n & 7) << 2) + ((k & 7) >> 1)) << 1) + ((k >> 3) & 1);
}

// ---------------- zero the padding rows (1000..1023) of qp/kp/vrow ------------
__global__ void zfill_kernel() {
    int bh = blockIdx.x;
    int t = threadIdx.x;
    for (int f = t; f < 768; f += 256) {
        int m = 1000 + (f >> 5);
        int k = (f & 31) << 1;
        g_qp[bh * 32768 + a_off16(m, k, 4)] = 0;
        g_kp[bh * 32768 + b_off16(k, m, 128)] = 0;
        g_vrow[bh * 32768 + m * 32 + (f & 31)] = 0;
    }
}

// ---------------- LayerNorm -> A-perm bf16 ------------------------------------
__global__ void ln_kernel(const float* __restrict__ x,
                          const float* __restrict__ gamma,
                          const float* __restrict__ beta) {
    int row = blockIdx.x;
    int tid = threadIdx.x;
    const float4 v = ((const float4*)(x + (size_t)row * ND))[tid];
    __shared__ float red[4];

    float s = v.x + v.y + v.z + v.w;
#pragma unroll
    for (int o = 16; o; o >>= 1) s += __shfl_xor_sync(0xffffffffu, s, o);
    if ((tid & 31) == 0) red[tid >> 5] = s;
    __syncthreads();
    float mean = (red[0] + red[1] + red[2] + red[3]) * (1.0f / ND);
    __syncthreads();

    float a = v.x - mean, b = v.y - mean, c = v.z - mean, d = v.w - mean;
    float s2 = a * a + b * b + c * c + d * d;
#pragma unroll
    for (int o = 16; o; o >>= 1) s2 += __shfl_xor_sync(0xffffffffu, s2, o);
    if ((tid & 31) == 0) red[tid >> 5] = s2;
    __syncthreads();
    float var = (red[0] + red[1] + red[2] + red[3]) * (1.0f / ND);
    float inv = rsqrtf(var + 1e-5f);

    const float4 gg = ((const float4*)gamma)[tid];
    const float4 bt = ((const float4*)beta)[tid];
    float o0 = a * inv * gg.x + bt.x;
    float o1 = b * inv * gg.y + bt.y;
    float o2 = c * inv * gg.z + bt.z;
    float o3 = d * inv * gg.w + bt.w;
    int k0 = tid << 2;
    g_xnp[a_off16(row, k0, 32)] = bf2(o0, o1);
    g_xnp[a_off16(row, k0 + 2, 32)] = bf2(o2, o3);
}

// ---------------- all 4 weights -> B-perm bf16 (one launch) -------------------
__global__ void wconv_kernel(const float* __restrict__ W0, const float* __restrict__ W1,
                             const float* __restrict__ W2, const float* __restrict__ W3) {
    int widx = blockIdx.y;
    const float* W = (widx == 0) ? W0 : (widx == 1) ? W1 : (widx == 2) ? W2 : W3;
    int idx = blockIdx.x * 256 + threadIdx.x;
    int n = idx >> 8, k = (idx & 255) << 1;
    g_wp[widx * 131072 + b_off16(k, n, 64)] =
        bf2(W[(size_t)n * ND + k], W[(size_t)n * ND + k + 1]);
}

// ---------------- rel * log2e -> B-perm bf16 (n = u_abs + 64, zero pad) -------
__global__ void relconv_kernel(const float* __restrict__ rel) {
    int idx = blockIdx.x * 256 + threadIdx.x;
    int u = idx >> 5, k = (idx & 31) << 1;
    int ua = u - 64;
    float a = 0.f, b = 0.f;
    if (ua >= 0 && ua < NRR) {
        a = rel[(size_t)ua * NDK + k] * LOG2E;
        b = rel[(size_t)ua * NDK + k + 1] * LOG2E;
    }
    g_relp[b_off16(k, u, 272)] = bf2(a, b);
}

// ---------------- streaming bf16 GEMM (no smem, no syncs) ---------------------
// outproj=0: gridDim.z picks q/k/v. outproj=1: f32 out + bias + residual.
__global__ void __launch_bounds__(256) gemm2_kernel(
    const float* __restrict__ b0, const float* __restrict__ b1,
    const float* __restrict__ b2, const float* __restrict__ resid,
    float* __restrict__ Cf, int outproj) {
    const int tid = threadIdx.x, lane = tid & 31, warp = tid >> 5;
    const int wm = warp >> 2, wn = warp & 3, g = lane >> 2, tig = lane & 3;
    const int m0 = blockIdx.y * 64, n0 = blockIdx.x * 128;
    const int z = blockIdx.z;
    const int mode = outproj ? 1 : (z == 0 ? 0 : (z == 1 ? 2 : 3));
    const int widx = outproj ? 3 : z;
    const float* bias = outproj ? b0 : (z == 0 ? b0 : (z == 1 ? b1 : b2));
    const unsigned* Ap = outproj ? g_ctxp : g_xnp;
    const unsigned* Ab = Ap + (size_t)(((m0 + wm * 32) >> 4) * 32) * 128 + (lane << 2);
    const unsigned* Bb = g_wp + (size_t)widx * 131072 + (size_t)((n0 >> 3) + wn * 4) * 64 + (lane << 1);

    float4 acc[2][4] = {};
    uint4 a[2][2];
    uint2 b[2][4];
    a[0][0] = *(const uint4*)(Ab);
    a[0][1] = *(const uint4*)(Ab + 4096);
#pragma unroll
    for (int j = 0; j < 4; j++) b[0][j] = *(const uint2*)(Bb + j * 64);
#pragma unroll
    for (int kt = 0; kt < 32; kt++) {
        int cur = kt & 1, nxt = cur ^ 1;
        if (kt < 31) {
            a[nxt][0] = *(const uint4*)(Ab + (kt + 1) * 128);
            a[nxt][1] = *(const uint4*)(Ab + 4096 + (kt + 1) * 128);
#pragma unroll
            for (int j = 0; j < 4; j++)
                b[nxt][j] = *(const uint2*)(Bb + (size_t)(kt + 1) * 4096 + j * 64);
        }
#pragma unroll
        for (int j = 0; j < 4; j++) {
            mma16(acc[0][j], a[cur][0], b[cur][j]);
            mma16(acc[1][j], a[cur][1], b[cur][j]);
        }
    }

    const float KS = 0.125f * LOG2E;
#pragma unroll
    for (int i = 0; i < 2; i++)
#pragma unroll
        for (int j = 0; j < 4; j++) {
            int col = n0 + wn * 32 + j * 8 + (tig << 1);
            float2 bb = *(const float2*)&bias[col];
            float4 c = acc[i][j];
            float cx = c.x + bb.x, cy = c.y + bb.y;
            float cz = c.z + bb.x, cw = c.w + bb.y;
            int r0 = m0 + wm * 32 + i * 16 + g, r1 = r0 + 8;
            if (mode == 1) {
                size_t o0 = (size_t)r0 * ND + col, o1 = (size_t)r1 * ND + col;
                float2 rr0 = *(const float2*)&resid[o0];
                float2 rr1 = *(const float2*)&resid[o1];
                *(float2*)&Cf[o0] = make_float2(cx + rr0.x, cy + rr0.y);
                *(float2*)&Cf[o1] = make_float2(cz + rr1.x, cw + rr1.y);
            } else {
                int h = col >> 6, d = col & 63;
                int b0i = r0 / NL, l0 = r0 - b0i * NL;
                int b1i = r1 / NL, l1 = r1 - b1i * NL;
                int bh0 = b0i * NH + h, bh1 = b1i * NH + h;
                if (mode == 0) {
                    g_qp[bh0 * 32768 + a_off16(l0, d, 4)] = bf2(cx, cy);
                    g_qp[bh1 * 32768 + a_off16(l1, d, 4)] = bf2(cz, cw);
                } else if (mode == 2) {
                    g_kp[bh0 * 32768 + b_off16(d, l0, 128)] = bf2(cx * KS, cy * KS);
                    g_kp[bh1 * 32768 + b_off16(d, l1, 128)] = bf2(cz * KS, cw * KS);
                } else {
                    g_vrow[bh0 * 32768 + l0 * 32 + (d >> 1)] = bf2(cx, cy);
                    g_vrow[bh1 * 32768 + l1 * 32 + (d >> 1)] = bf2(cz, cw);
                }
            }
        }
}

// ---------------- flash attention: S2 ring buffer + fused S1/S2 loop ----------
// smem words: V 2x2048 | P 2048 | S1 64x68 | S2ring 64x128 | m/l/a
#define OFF_V 0
#define OFF_P 4096
#define OFF_S1 6144
#define OFF_S2 10496
#define OFF_M 18688
#define OFF_L 18752
#define OFF_A 18816
#define ATTN_WORDS (18816 + 64)
#define ATTN_SMEM_BYTES (ATTN_WORDS * 4)

__global__ void __launch_bounds__(256) attn_kernel() {
    extern __shared__ float sm[];
    unsigned* Vs = (unsigned*)sm + OFF_V;
    unsigned* Ps = (unsigned*)sm + OFF_P;
    float* S1s = sm + OFF_S1;
    float* S2r = sm + OFF_S2;      // ring: [64][128], slot = v & 127
    float* row_m = sm + OFF_M;
    float* row_l = sm + OFF_L;
    float* row_a = sm + OFF_A;

    const int it = blockIdx.x, bh = blockIdx.y;
    const int bq = bh >> 3, h = bh & 7;
    const int i0 = it << 6;
    const int tid = threadIdx.x;
    const int lane = tid & 31, warp = tid >> 5;
    const int g = lane >> 2, tig = lane & 3;

    const unsigned* qpb = g_qp + bh * 32768;
    const unsigned* kpb = g_kp + bh * 32768;
    const unsigned* vrb = g_vrow + bh * 32768;

    if (tid < 64) { row_m[tid] = -1e30f; row_l[tid] = 0.f; }
    float4 O[4] = {};
    __syncthreads();

    for (int jt = 0; jt < 16; jt++) {
        const int j0 = jt << 6;
        unsigned* Vbuf = Vs + ((jt & 1) << 11);

        // stage V tile: row-major bf16 -> B-perm (pair over j via prmt)
#pragma unroll
        for (int i = 0; i < 4; i++) {
            int f = tid + (i << 8);
            int rp = f >> 5, c2 = f & 31;
            unsigned wa = vrb[(j0 + (rp << 1)) * 32 + c2];
            unsigned wb = vrb[(j0 + (rp << 1) + 1) * 32 + c2];
            Vbuf[b_off16(rp << 1, c2 << 1, 8)] = prmt(wa, wb, 0x5410);
            Vbuf[b_off16(rp << 1, (c2 << 1) + 1, 8)] = prmt(wa, wb, 0x7632);
        }

        // fused S1 + S2(ring): each Q fragment loaded once, feeds both
        {
            // ring tiles: jt==0 -> v in [0,128) (2 per warp); else [j0+64, j0+128)
            const int vt_a = (jt == 0) ? (warp << 3) : (j0 + 64 + (warp << 3));
            const int vt_b = 64 + (warp << 3);                     // jt==0 only
            const int na = vt_a + 1000 - i0, nb = vt_b + 1000 - i0;
            float4 s1[4] = {}, s2a[4] = {}, s2b[4] = {};
#pragma unroll
            for (int kt = 0; kt < 4; kt++) {
                uint2 bk = *(const uint2*)(kpb + (size_t)(kt * 128 + (jt << 3) + warp) * 64 + (lane << 1));
                uint2 ba = *(const uint2*)(g_relp + (size_t)(kt * 272 + (na >> 3)) * 64 + (lane << 1));
                uint2 bb = *(const uint2*)(g_relp + (size_t)(kt * 272 + (nb >> 3)) * 64 + (lane << 1));
#pragma unroll
                for (int mt = 0; mt < 4; mt++) {
                    uint4 afr = *(const uint4*)(qpb + (size_t)(((it << 2) + mt) * 4 + kt) * 128 + (lane << 2));
                    mma16(s1[mt], afr, bk);
                    mma16(s2a[mt], afr, ba);
                    if (jt == 0) mma16(s2b[mt], afr, bb);
                }
            }
            int col = (warp << 3) + (tig << 1);
            int ca = (vt_a & 127) + (tig << 1);
#pragma unroll
            for (int mt = 0; mt < 4; mt++) {
                int r0 = (mt << 4) + g;
                *(float2*)&S1s[r0 * 68 + col] = make_float2(s1[mt].x, s1[mt].y);
                *(float2*)&S1s[(r0 + 8) * 68 + col] = make_float2(s1[mt].z, s1[mt].w);
                *(float2*)&S2r[(r0 << 7) + ca] = make_float2(s2a[mt].x, s2a[mt].y);
                *(float2*)&S2r[((r0 + 8) << 7) + ca] = make_float2(s2a[mt].z, s2a[mt].w);
                if (jt == 0) {
                    int cb = vt_b + (tig << 1);
                    *(float2*)&S2r[(r0 << 7) + cb] = make_float2(s2b[mt].x, s2b[mt].y);
                    *(float2*)&S2r[((r0 + 8) << 7) + cb] = make_float2(s2b[mt].z, s2b[mt].w);
                }
            }
        }
        __syncthreads();

        // online softmax (exp2 domain) with ring gather
        {
            int i = tid >> 2, q = tid & 3;
            int cbase = q << 4;
            float e[16];
            float mx = -1e30f;
#pragma unroll
            for (int c = 0; c < 16; c++) {
                int cc = cbase + c;
                float s = S1s[i * 68 + cc] + S2r[(i << 7) + ((j0 + cc - i + 63) & 127)];
                e[c] = (j0 + cc >= NL) ? -1e30f : s;
                mx = fmaxf(mx, e[c]);
            }
            mx = fmaxf(mx, __shfl_xor_sync(0xffffffffu, mx, 1));
            mx = fmaxf(mx, __shfl_xor_sync(0xffffffffu, mx, 2));
            float mold = row_m[i];
            float mnew = fmaxf(mold, mx);
            float alpha = ex2f(mold - mnew);
            float ssum = 0.f;
#pragma unroll
            for (int c = 0; c < 16; c++) {
                float ev = ex2f(e[c] - mnew);
                e[c] = ev;
                ssum += ev;
            }
#pragma unroll
            for (int p = 0; p < 8; p++)
                Ps[a_off16(i, cbase + (p << 1), 4)] = bf2(e[p << 1], e[(p << 1) + 1]);
            ssum += __shfl_xor_sync(0xffffffffu, ssum, 1);
            ssum += __shfl_xor_sync(0xffffffffu, ssum, 2);
            if (q == 0) {
                row_m[i] = mnew;
                row_a[i] = alpha;
                row_l[i] = row_l[i] * alpha + ssum;
            }
        }
        __syncthreads();

        // rescale O, then O += P @ V
        {
#pragma unroll
            for (int mt = 0; mt < 4; mt++) {
                float a0 = row_a[(mt << 4) + g];
                float a1 = row_a[(mt << 4) + 8 + g];
                O[mt].x *= a0; O[mt].y *= a0;
                O[mt].z *= a1; O[mt].w *= a1;
            }
#pragma unroll
            for (int kt = 0; kt < 4; kt++) {
                uint2 bfr = *(uint2*)&Vbuf[((kt * 8 + warp) << 6) + (lane << 1)];
#pragma unroll
                for (int mt = 0; mt < 4; mt++) {
                    uint4 afr = *(uint4*)&Ps[((mt * 4 + kt) << 7) + (lane << 2)];
                    mma16(O[mt], afr, bfr);
                }
            }
        }
    }

    // normalize + write ctx as A-perm bf16
#pragma unroll
    for (int mt = 0; mt < 4; mt++) {
        int r0 = (mt << 4) + g, r1 = r0 + 8;
        int col = (warp << 3) + (tig << 1);
        if (i0 + r0 < NL) {
            float inv = 1.f / row_l[r0];
            int gm = bq * NL + i0 + r0;
            g_ctxp[a_off16(gm, (h << 6) + col, 32)] = bf2(O[mt].x * inv, O[mt].y * inv);
        }
        if (i0 + r1 < NL) {
            float inv = 1.f / row_l[r1];
            int gm = bq * NL + i0 + r1;
            g_ctxp[a_off16(gm, (h << 6) + col, 32)] = bf2(O[mt].z * inv, O[mt].w * inv);
        }
    }
}

// ---------------- launch ------------------------------------------------------
extern "C" void kernel_launch(void* const* d_in, const int* in_sizes, int n_in,
                              void* d_out, int out_size) {
    const float* x     = (const float*)d_in[0];
    const float* Wq    = (const float*)d_in[1];
    const float* bq    = (const float*)d_in[2];
    const float* Wk    = (const float*)d_in[3];
    const float* bk    = (const float*)d_in[4];
    const float* Wv    = (const float*)d_in[5];
    const float* bv    = (const float*)d_in[6];
    const float* Wo    = (const float*)d_in[7];
    const float* bo    = (const float*)d_in[8];
    const float* rel   = (const float*)d_in[9];
    const float* gamma = (const float*)d_in[10];
    const float* beta  = (const float*)d_in[11];
    float* out = (float*)d_out;

    cudaFuncSetAttribute(attn_kernel, cudaFuncAttributeMaxDynamicSharedMemorySize,
                         ATTN_SMEM_BYTES);

    zfill_kernel<<<NBH, 256>>>();
    ln_kernel<<<8 * NL, 128>>>(x, gamma, beta);
    wconv_kernel<<<dim3(512, 4), 256>>>(Wq, Wk, Wv, Wo);
    relconv_kernel<<<272, 256>>>(rel);

    gemm2_kernel<<<dim3(4, 125, 3), 256>>>(bq, bk, bv, nullptr, nullptr, 0);  // QKV
    attn_kernel<<<dim3(16, NBH), 256, ATTN_SMEM_BYTES>>>();
    gemm2_kernel<<<dim3(4, 125, 1), 256>>>(bo, nullptr, nullptr, x, out, 1);  // out-proj
}

// round 9
// speedup vs baseline: 1.6400x; 1.0899x over previous
#include <cuda_runtime.h>
#include <cuda_bf16.h>

#define NL 1000
#define ND 512
#define NH 8
#define NDK 64
#define NRR 1999
#define NBH 64
#define LOG2E 1.4426950408889634f

// ---------------- device scratch: pre-permuted bf16 fragment arrays -----------
__device__ unsigned g_xnp [500 * 32 * 128];   // xn  A-perm (8000 x 512)
__device__ unsigned g_ctxp[500 * 32 * 128];   // ctx A-perm (8000 x 512)
__device__ unsigned g_wp  [4 * 131072];       // W   B-perm (512k x 512n) x4
__device__ unsigned g_qp  [NBH * 32768];      // q per bh: A-perm (1024 x 64)
__device__ unsigned g_kp  [NBH * 32768];      // k per bh: B-perm k=d, n=j (x0.125*log2e)
__device__ unsigned g_vrow[NBH * 32768];      // v per bh: row-major bf16 (1024 x 64)
__device__ unsigned g_relp[4 * 272 * 64];     // rel*log2e B-perm k=d, n=u_abs+64

// ---------------- helpers -----------------------------------------------------
__device__ __forceinline__ unsigned bf2(float lo, float hi) {
    unsigned r;
    asm("cvt.rn.bf16x2.f32 %0, %1, %2;" : "=r"(r) : "f"(hi), "f"(lo));
    return r;
}
__device__ __forceinline__ unsigned prmt(unsigned a, unsigned b, unsigned sel) {
    unsigned r;
    asm("prmt.b32 %0, %1, %2, %3;" : "=r"(r) : "r"(a), "r"(b), "r"(sel));
    return r;
}
__device__ __forceinline__ float ex2f(float x) {
    float r;
    asm("ex2.approx.ftz.f32 %0, %1;" : "=f"(r) : "f"(x));
    return r;
}
__device__ __forceinline__ void mma16(float4& d, uint4 a, uint2 b) {
    asm volatile(
        "mma.sync.aligned.m16n8k16.row.col.f32.bf16.bf16.f32 "
        "{%0,%1,%2,%3}, {%4,%5,%6,%7}, {%8,%9}, {%0,%1,%2,%3};\n"
        : "+f"(d.x), "+f"(d.y), "+f"(d.z), "+f"(d.w)
        : "r"(a.x), "r"(a.y), "r"(a.z), "r"(a.w), "r"(b.x), "r"(b.y));
}
__device__ __forceinline__ int a_off16(int m, int k, int nkt16) {
    return (((m >> 4) * nkt16 + (k >> 4)) << 7) +
           ((((m & 7) << 2) + ((k & 7) >> 1)) << 2) + ((m >> 3) & 1) + (((k >> 3) & 1) << 1);
}
__device__ __forceinline__ int b_off16(int k, int n, int nnt) {
    return (((k >> 4) * nnt + (n >> 3)) << 6) +
           ((((n & 7) << 2) + ((k & 7) >> 1)) << 1) + ((k >> 3) & 1);
}

// ---------------- zero the padding rows (1000..1023) of qp/kp/vrow ------------
__global__ void zfill_kernel() {
    int bh = blockIdx.x;
    int t = threadIdx.x;
    for (int f = t; f < 768; f += 256) {
        int m = 1000 + (f >> 5);
        int k = (f & 31) << 1;
        g_qp[bh * 32768 + a_off16(m, k, 4)] = 0;
        g_kp[bh * 32768 + b_off16(k, m, 128)] = 0;
        g_vrow[bh * 32768 + m * 32 + (f & 31)] = 0;
    }
}

// ---------------- LayerNorm -> A-perm bf16 ------------------------------------
__global__ void ln_kernel(const float* __restrict__ x,
                          const float* __restrict__ gamma,
                          const float* __restrict__ beta) {
    int row = blockIdx.x;
    int tid = threadIdx.x;
    const float4 v = ((const float4*)(x + (size_t)row * ND))[tid];
    __shared__ float red[4];

    float s = v.x + v.y + v.z + v.w;
#pragma unroll
    for (int o = 16; o; o >>= 1) s += __shfl_xor_sync(0xffffffffu, s, o);
    if ((tid & 31) == 0) red[tid >> 5] = s;
    __syncthreads();
    float mean = (red[0] + red[1] + red[2] + red[3]) * (1.0f / ND);
    __syncthreads();

    float a = v.x - mean, b = v.y - mean, c = v.z - mean, d = v.w - mean;
    float s2 = a * a + b * b + c * c + d * d;
#pragma unroll
    for (int o = 16; o; o >>= 1) s2 += __shfl_xor_sync(0xffffffffu, s2, o);
    if ((tid & 31) == 0) red[tid >> 5] = s2;
    __syncthreads();
    float var = (red[0] + red[1] + red[2] + red[3]) * (1.0f / ND);
    float inv = rsqrtf(var + 1e-5f);

    const float4 gg = ((const float4*)gamma)[tid];
    const float4 bt = ((const float4*)beta)[tid];
    float o0 = a * inv * gg.x + bt.x;
    float o1 = b * inv * gg.y + bt.y;
    float o2 = c * inv * gg.z + bt.z;
    float o3 = d * inv * gg.w + bt.w;
    int k0 = tid << 2;
    g_xnp[a_off16(row, k0, 32)] = bf2(o0, o1);
    g_xnp[a_off16(row, k0 + 2, 32)] = bf2(o2, o3);
}

// ---------------- all 4 weights -> B-perm bf16 (one launch) -------------------
__global__ void wconv_kernel(const float* __restrict__ W0, const float* __restrict__ W1,
                             const float* __restrict__ W2, const float* __restrict__ W3) {
    int widx = blockIdx.y;
    const float* W = (widx == 0) ? W0 : (widx == 1) ? W1 : (widx == 2) ? W2 : W3;
    int idx = blockIdx.x * 256 + threadIdx.x;
    int n = idx >> 8, k = (idx & 255) << 1;
    g_wp[widx * 131072 + b_off16(k, n, 64)] =
        bf2(W[(size_t)n * ND + k], W[(size_t)n * ND + k + 1]);
}

// ---------------- rel * log2e -> B-perm bf16 (n = u_abs + 64, zero pad) -------
__global__ void relconv_kernel(const float* __restrict__ rel) {
    int idx = blockIdx.x * 256 + threadIdx.x;
    int u = idx >> 5, k = (idx & 31) << 1;
    int ua = u - 64;
    float a = 0.f, b = 0.f;
    if (ua >= 0 && ua < NRR) {
        a = rel[(size_t)ua * NDK + k] * LOG2E;
        b = rel[(size_t)ua * NDK + k + 1] * LOG2E;
    }
    g_relp[b_off16(k, u, 272)] = bf2(a, b);
}

// ---------------- streaming bf16 GEMM (no smem, no syncs) ---------------------
__global__ void __launch_bounds__(256) gemm2_kernel(
    const float* __restrict__ b0, const float* __restrict__ b1,
    const float* __restrict__ b2, const float* __restrict__ resid,
    float* __restrict__ Cf, int outproj) {
    const int tid = threadIdx.x, lane = tid & 31, warp = tid >> 5;
    const int wm = warp >> 2, wn = warp & 3, g = lane >> 2, tig = lane & 3;
    const int m0 = blockIdx.y * 64, n0 = blockIdx.x * 128;
    const int z = blockIdx.z;
    const int mode = outproj ? 1 : (z == 0 ? 0 : (z == 1 ? 2 : 3));
    const int widx = outproj ? 3 : z;
    const float* bias = outproj ? b0 : (z == 0 ? b0 : (z == 1 ? b1 : b2));
    const unsigned* Ap = outproj ? g_ctxp : g_xnp;
    const unsigned* Ab = Ap + (size_t)(((m0 + wm * 32) >> 4) * 32) * 128 + (lane << 2);
    const unsigned* Bb = g_wp + (size_t)widx * 131072 + (size_t)((n0 >> 3) + wn * 4) * 64 + (lane << 1);

    float4 acc[2][4] = {};
    uint4 a[2][2];
    uint2 b[2][4];
    a[0][0] = *(const uint4*)(Ab);
    a[0][1] = *(const uint4*)(Ab + 4096);
#pragma unroll
    for (int j = 0; j < 4; j++) b[0][j] = *(const uint2*)(Bb + j * 64);
#pragma unroll
    for (int kt = 0; kt < 32; kt++) {
        int cur = kt & 1, nxt = cur ^ 1;
        if (kt < 31) {
            a[nxt][0] = *(const uint4*)(Ab + (kt + 1) * 128);
            a[nxt][1] = *(const uint4*)(Ab + 4096 + (kt + 1) * 128);
#pragma unroll
            for (int j = 0; j < 4; j++)
                b[nxt][j] = *(const uint2*)(Bb + (size_t)(kt + 1) * 4096 + j * 64);
        }
#pragma unroll
        for (int j = 0; j < 4; j++) {
            mma16(acc[0][j], a[cur][0], b[cur][j]);
            mma16(acc[1][j], a[cur][1], b[cur][j]);
        }
    }

    const float KS = 0.125f * LOG2E;
#pragma unroll
    for (int i = 0; i < 2; i++)
#pragma unroll
        for (int j = 0; j < 4; j++) {
            int col = n0 + wn * 32 + j * 8 + (tig << 1);
            float2 bb = *(const float2*)&bias[col];
            float4 c = acc[i][j];
            float cx = c.x + bb.x, cy = c.y + bb.y;
            float cz = c.z + bb.x, cw = c.w + bb.y;
            int r0 = m0 + wm * 32 + i * 16 + g, r1 = r0 + 8;
            if (mode == 1) {
                size_t o0 = (size_t)r0 * ND + col, o1 = (size_t)r1 * ND + col;
                float2 rr0 = *(const float2*)&resid[o0];
                float2 rr1 = *(const float2*)&resid[o1];
                *(float2*)&Cf[o0] = make_float2(cx + rr0.x, cy + rr0.y);
                *(float2*)&Cf[o1] = make_float2(cz + rr1.x, cw + rr1.y);
            } else {
                int h = col >> 6, d = col & 63;
                int b0i = r0 / NL, l0 = r0 - b0i * NL;
                int b1i = r1 / NL, l1 = r1 - b1i * NL;
                int bh0 = b0i * NH + h, bh1 = b1i * NH + h;
                if (mode == 0) {
                    g_qp[bh0 * 32768 + a_off16(l0, d, 4)] = bf2(cx, cy);
                    g_qp[bh1 * 32768 + a_off16(l1, d, 4)] = bf2(cz, cw);
                } else if (mode == 2) {
                    g_kp[bh0 * 32768 + b_off16(d, l0, 128)] = bf2(cx * KS, cy * KS);
                    g_kp[bh1 * 32768 + b_off16(d, l1, 128)] = bf2(cz * KS, cw * KS);
                } else {
                    g_vrow[bh0 * 32768 + l0 * 32 + (d >> 1)] = bf2(cx, cy);
                    g_vrow[bh1 * 32768 + l1 * 32 + (d >> 1)] = bf2(cz, cw);
                }
            }
        }
}

// ---------------- flash attention: fragment-resident softmax ------------------
// smem words: V 2x2048 | P 2048 | S2ring 64x128 | redM 64x8 | redS 64x8 | m | l
#define OFF_V 0
#define OFF_P 4096
#define OFF_S2 6144
#define OFF_RM 14336
#define OFF_RS 14848
#define OFF_M 15360
#define OFF_L 15424
#define ATTN_WORDS 15488
#define ATTN_SMEM_BYTES (ATTN_WORDS * 4)

__global__ void __launch_bounds__(256) attn_kernel() {
    extern __shared__ float sm[];
    unsigned* Vs = (unsigned*)sm + OFF_V;
    unsigned* Ps = (unsigned*)sm + OFF_P;
    float* S2r = sm + OFF_S2;      // ring: [64][128], slot = v & 127
    float* redM = sm + OFF_RM;     // [64][8] row-max partials per warp
    float* redS = sm + OFF_RS;     // [64][8] row-sum partials per warp
    float* row_m = sm + OFF_M;
    float* row_l = sm + OFF_L;

    const int it = blockIdx.x, bh = blockIdx.y;
    const int bq = bh >> 3, h = bh & 7;
    const int i0 = it << 6;
    const int tid = threadIdx.x;
    const int lane = tid & 31, warp = tid >> 5;
    const int g = lane >> 2, tig = lane & 3;
    const int c0 = (warp << 3) + (tig << 1);

    const unsigned* qpb = g_qp + bh * 32768;
    const unsigned* kpb = g_kp + bh * 32768;
    const unsigned* vrb = g_vrow + bh * 32768;

    if (tid < 64) { row_m[tid] = -1e30f; row_l[tid] = 0.f; }
    float4 O[4] = {};
    __syncthreads();

    for (int jt = 0; jt < 16; jt++) {
        const int j0 = jt << 6;
        unsigned* Vbuf = Vs + ((jt & 1) << 11);

        // stage V tile: row-major bf16 -> B-perm (pair over j via prmt)
#pragma unroll
        for (int i = 0; i < 4; i++) {
            int f = tid + (i << 8);
            int rp = f >> 5, c2 = f & 31;
            unsigned wa = vrb[(j0 + (rp << 1)) * 32 + c2];
            unsigned wb = vrb[(j0 + (rp << 1) + 1) * 32 + c2];
            Vbuf[b_off16(rp << 1, c2 << 1, 8)] = prmt(wa, wb, 0x5410);
            Vbuf[b_off16(rp << 1, (c2 << 1) + 1, 8)] = prmt(wa, wb, 0x7632);
        }

        // fused S1 + S2(ring) mma: each Q fragment loaded once
        float4 s1[4];
        {
            const int vt_a = (jt == 0) ? (warp << 3) : (j0 + 64 + (warp << 3));
            const int vt_b = 64 + (warp << 3);                 // jt==0 only
            const int na = vt_a + 1000 - i0, nb = vt_b + 1000 - i0;
            float4 s2a[4] = {}, s2b[4] = {};
#pragma unroll
            for (int mt = 0; mt < 4; mt++) s1[mt] = make_float4(0.f, 0.f, 0.f, 0.f);
#pragma unroll
            for (int kt = 0; kt < 4; kt++) {
                uint2 bk = *(const uint2*)(kpb + (size_t)(kt * 128 + (jt << 3) + warp) * 64 + (lane << 1));
                uint2 ba = *(const uint2*)(g_relp + (size_t)(kt * 272 + (na >> 3)) * 64 + (lane << 1));
                uint2 bb = *(const uint2*)(g_relp + (size_t)(kt * 272 + (nb >> 3)) * 64 + (lane << 1));
#pragma unroll
                for (int mt = 0; mt < 4; mt++) {
                    uint4 afr = *(const uint4*)(qpb + (size_t)(((it << 2) + mt) * 4 + kt) * 128 + (lane << 2));
                    mma16(s1[mt], afr, bk);
                    mma16(s2a[mt], afr, ba);
                    if (jt == 0) mma16(s2b[mt], afr, bb);
                }
            }
            int ca = (vt_a & 127) + (tig << 1);
#pragma unroll
            for (int mt = 0; mt < 4; mt++) {
                int r0 = (mt << 4) + g;
                *(float2*)&S2r[(r0 << 7) + ca] = make_float2(s2a[mt].x, s2a[mt].y);
                *(float2*)&S2r[((r0 + 8) << 7) + ca] = make_float2(s2a[mt].z, s2a[mt].w);
                if (jt == 0) {
                    int cb = vt_b + (tig << 1);
                    *(float2*)&S2r[(r0 << 7) + cb] = make_float2(s2b[mt].x, s2b[mt].y);
                    *(float2*)&S2r[((r0 + 8) << 7) + cb] = make_float2(s2b[mt].z, s2b[mt].w);
                }
            }
        }
        __syncthreads();   // A: ring visible

        // phase A: gather S2 into fragments, mask, row-max partials
#pragma unroll
        for (int mt = 0; mt < 4; mt++) {
            int r0 = (mt << 4) + g, r1 = r0 + 8;
            int b0 = j0 - r0 + 63;
            s1[mt].x += S2r[(r0 << 7) + ((b0 + c0) & 127)];
            s1[mt].y += S2r[(r0 << 7) + ((b0 + c0 + 1) & 127)];
            s1[mt].z += S2r[(r1 << 7) + ((b0 - 8 + c0) & 127)];
            s1[mt].w += S2r[(r1 << 7) + ((b0 - 8 + c0 + 1) & 127)];
            if (j0 + c0 >= NL) { s1[mt].x = -1e30f; s1[mt].z = -1e30f; }
            if (j0 + c0 + 1 >= NL) { s1[mt].y = -1e30f; s1[mt].w = -1e30f; }
            float m0 = fmaxf(s1[mt].x, s1[mt].y);
            float m1 = fmaxf(s1[mt].z, s1[mt].w);
            m0 = fmaxf(m0, __shfl_xor_sync(0xffffffffu, m0, 1));
            m0 = fmaxf(m0, __shfl_xor_sync(0xffffffffu, m0, 2));
            m1 = fmaxf(m1, __shfl_xor_sync(0xffffffffu, m1, 1));
            m1 = fmaxf(m1, __shfl_xor_sync(0xffffffffu, m1, 2));
            if (tig == 0) {
                redM[(r0 << 3) + warp] = m0;
                redM[(r1 << 3) + warp] = m1;
            }
        }
        __syncthreads();   // B: row-max partials visible

        // phase B: mnew/alpha (local), exp, write P fragments, row-sum partials
        float al[4], ah[4];
#pragma unroll
        for (int mt = 0; mt < 4; mt++) {
            int r0 = (mt << 4) + g, r1 = r0 + 8;
            float4 p0 = *(float4*)&redM[r0 << 3];
            float4 p1 = *(float4*)&redM[(r0 << 3) + 4];
            float mp0 = fmaxf(fmaxf(fmaxf(p0.x, p0.y), fmaxf(p0.z, p0.w)),
                              fmaxf(fmaxf(p1.x, p1.y), fmaxf(p1.z, p1.w)));
            float4 q0 = *(float4*)&redM[r1 << 3];
            float4 q1 = *(float4*)&redM[(r1 << 3) + 4];
            float mp1 = fmaxf(fmaxf(fmaxf(q0.x, q0.y), fmaxf(q0.z, q0.w)),
                              fmaxf(fmaxf(q1.x, q1.y), fmaxf(q1.z, q1.w)));
            float mold0 = row_m[r0], mold1 = row_m[r1];
            float mn0 = fmaxf(mold0, mp0), mn1 = fmaxf(mold1, mp1);
            al[mt] = ex2f(mold0 - mn0);
            ah[mt] = ex2f(mold1 - mn1);
            float e00 = ex2f(s1[mt].x - mn0), e01 = ex2f(s1[mt].y - mn0);
            float e10 = ex2f(s1[mt].z - mn1), e11 = ex2f(s1[mt].w - mn1);
            Ps[a_off16(r0, c0, 4)] = bf2(e00, e01);
            Ps[a_off16(r1, c0, 4)] = bf2(e10, e11);
            float s0 = e00 + e01, sh = e10 + e11;
            s0 += __shfl_xor_sync(0xffffffffu, s0, 1);
            s0 += __shfl_xor_sync(0xffffffffu, s0, 2);
            sh += __shfl_xor_sync(0xffffffffu, sh, 1);
            sh += __shfl_xor_sync(0xffffffffu, sh, 2);
            if (tig == 0) {
                redS[(r0 << 3) + warp] = s0;
                redS[(r1 << 3) + warp] = sh;
            }
        }
        __syncthreads();   // C: P + sum partials visible

        // owner updates per-row softmax state
        if (tid < 64) {
            int i = tid;
            float4 p0 = *(float4*)&redM[i << 3];
            float4 p1 = *(float4*)&redM[(i << 3) + 4];
            float mp = fmaxf(fmaxf(fmaxf(p0.x, p0.y), fmaxf(p0.z, p0.w)),
                             fmaxf(fmaxf(p1.x, p1.y), fmaxf(p1.z, p1.w)));
            float mold = row_m[i];
            float mnew = fmaxf(mold, mp);
            float4 s0 = *(float4*)&redS[i << 3];
            float4 s1v = *(float4*)&redS[(i << 3) + 4];
            float ssum = s0.x + s0.y + s0.z + s0.w + s1v.x + s1v.y + s1v.z + s1v.w;
            row_l[i] = row_l[i] * ex2f(mold - mnew) + ssum;
            row_m[i] = mnew;
        }

        // rescale O (local alphas), then O += P @ V
#pragma unroll
        for (int mt = 0; mt < 4; mt++) {
            O[mt].x *= al[mt]; O[mt].y *= al[mt];
            O[mt].z *= ah[mt]; O[mt].w *= ah[mt];
        }
#pragma unroll
        for (int kt = 0; kt < 4; kt++) {
            uint2 bfr = *(uint2*)&Vbuf[((kt * 8 + warp) << 6) + (lane << 1)];
#pragma unroll
            for (int mt = 0; mt < 4; mt++) {
                uint4 afr = *(uint4*)&Ps[((mt * 4 + kt) << 7) + (lane << 2)];
                mma16(O[mt], afr, bfr);
            }
        }
    }

    __syncthreads();
    // normalize + write ctx as A-perm bf16
#pragma unroll
    for (int mt = 0; mt < 4; mt++) {
        int r0 = (mt << 4) + g, r1 = r0 + 8;
        int col = (warp << 3) + (tig << 1);
        if (i0 + r0 < NL) {
            float inv = 1.f / row_l[r0];
            int gm = bq * NL + i0 + r0;
            g_ctxp[a_off16(gm, (h << 6) + col, 32)] = bf2(O[mt].x * inv, O[mt].y * inv);
        }
        if (i0 + r1 < NL) {
            float inv = 1.f / row_l[r1];
            int gm = bq * NL + i0 + r1;
            g_ctxp[a_off16(gm, (h << 6) + col, 32)] = bf2(O[mt].z * inv, O[mt].w * inv);
        }
    }
}

// ---------------- launch ------------------------------------------------------
extern "C" void kernel_launch(void* const* d_in, const int* in_sizes, int n_in,
                              void* d_out, int out_size) {
    const float* x     = (const float*)d_in[0];
    const float* Wq    = (const float*)d_in[1];
    const float* bq    = (const float*)d_in[2];
    const float* Wk    = (const float*)d_in[3];
    const float* bk    = (const float*)d_in[4];
    const float* Wv    = (const float*)d_in[5];
    const float* bv    = (const float*)d_in[6];
    const float* Wo    = (const float*)d_in[7];
    const float* bo    = (const float*)d_in[8];
    const float* rel   = (const float*)d_in[9];
    const float* gamma = (const float*)d_in[10];
    const float* beta  = (const float*)d_in[11];
    float* out = (float*)d_out;

    cudaFuncSetAttribute(attn_kernel, cudaFuncAttributeMaxDynamicSharedMemorySize,
                         ATTN_SMEM_BYTES);

    zfill_kernel<<<NBH, 256>>>();
    ln_kernel<<<8 * NL, 128>>>(x, gamma, beta);
    wconv_kernel<<<dim3(512, 4), 256>>>(Wq, Wk, Wv, Wo);
    relconv_kernel<<<272, 256>>>(rel);

    gemm2_kernel<<<dim3(4, 125, 3), 256>>>(bq, bk, bv, nullptr, nullptr, 0);  // QKV
    attn_kernel<<<dim3(16, NBH), 256, ATTN_SMEM_BYTES>>>();
    gemm2_kernel<<<dim3(4, 125, 1), 256>>>(bo, nullptr, nullptr, x, out, 1);  // out-proj
}

// round 10
// speedup vs baseline: 1.7427x; 1.0626x over previous
#include <cuda_runtime.h>
#include <cuda_bf16.h>

#define NL 1000
#define ND 512
#define NH 8
#define NDK 64
#define NRR 1999
#define NBH 64
#define LOG2E 1.4426950408889634f

// ---------------- device scratch: pre-permuted bf16 fragment arrays -----------
__device__ unsigned g_xnp [500 * 32 * 128];   // xn  A-perm (8000 x 512)
__device__ unsigned g_ctxp[500 * 32 * 128];   // ctx A-perm (8000 x 512)
__device__ unsigned g_wp  [4 * 131072];       // W   B-perm (512k x 512n) x4
__device__ unsigned g_qp  [NBH * 32768];      // q per bh: A-perm (1024 x 64)
__device__ unsigned g_kp  [NBH * 32768];      // k per bh: B-perm k=d, n=j (x0.125*log2e)
__device__ unsigned g_vrow[NBH * 32768];      // v per bh: row-major bf16 (1024 x 64)
__device__ unsigned g_relp[4 * 272 * 64];     // rel*log2e B-perm k=d, n=u_abs+64

// ---------------- helpers -----------------------------------------------------
__device__ __forceinline__ unsigned bf2(float lo, float hi) {
    unsigned r;
    asm("cvt.rn.bf16x2.f32 %0, %1, %2;" : "=r"(r) : "f"(hi), "f"(lo));
    return r;
}
__device__ __forceinline__ unsigned prmt(unsigned a, unsigned b, unsigned sel) {
    unsigned r;
    asm("prmt.b32 %0, %1, %2, %3;" : "=r"(r) : "r"(a), "r"(b), "r"(sel));
    return r;
}
__device__ __forceinline__ float ex2f(float x) {
    float r;
    asm("ex2.approx.ftz.f32 %0, %1;" : "=f"(r) : "f"(x));
    return r;
}
__device__ __forceinline__ void mma16(float4& d, uint4 a, uint2 b) {
    asm volatile(
        "mma.sync.aligned.m16n8k16.row.col.f32.bf16.bf16.f32 "
        "{%0,%1,%2,%3}, {%4,%5,%6,%7}, {%8,%9}, {%0,%1,%2,%3};\n"
        : "+f"(d.x), "+f"(d.y), "+f"(d.z), "+f"(d.w)
        : "r"(a.x), "r"(a.y), "r"(a.z), "r"(a.w), "r"(b.x), "r"(b.y));
}
__device__ __forceinline__ int a_off16(int m, int k, int nkt16) {
    return (((m >> 4) * nkt16 + (k >> 4)) << 7) +
           ((((m & 7) << 2) + ((k & 7) >> 1)) << 2) + ((m >> 3) & 1) + (((k >> 3) & 1) << 1);
}
__device__ __forceinline__ int b_off16(int k, int n, int nnt) {
    return (((k >> 4) * nnt + (n >> 3)) << 6) +
           ((((n & 7) << 2) + ((k & 7) >> 1)) << 1) + ((k >> 3) & 1);
}

// ---------------- fused preamble: wconv(4) + relconv + zfill ------------------
__global__ void prep_kernel(const float* __restrict__ W0, const float* __restrict__ W1,
                            const float* __restrict__ W2, const float* __restrict__ W3,
                            const float* __restrict__ rel) {
    int bid = blockIdx.x;
    if (bid < 2048) {
        int widx = bid >> 9;
        const float* W = (widx == 0) ? W0 : (widx == 1) ? W1 : (widx == 2) ? W2 : W3;
        int idx = ((bid & 511) << 8) + threadIdx.x;
        int n = idx >> 8, k = (idx & 255) << 1;
        g_wp[widx * 131072 + b_off16(k, n, 64)] =
            bf2(W[(size_t)n * ND + k], W[(size_t)n * ND + k + 1]);
    } else if (bid < 2320) {
        int idx = ((bid - 2048) << 8) + threadIdx.x;    // 69632 words
        int u = idx >> 5, k = (idx & 31) << 1;
        int ua = u - 64;
        float a = 0.f, b = 0.f;
        if (ua >= 0 && ua < NRR) {
            a = rel[(size_t)ua * NDK + k] * LOG2E;
            b = rel[(size_t)ua * NDK + k + 1] * LOG2E;
        }
        g_relp[b_off16(k, u, 272)] = bf2(a, b);
    } else {
        int bh = bid - 2320;
        int t = threadIdx.x;
        for (int f = t; f < 768; f += 256) {
            int m = 1000 + (f >> 5);
            int k = (f & 31) << 1;
            g_qp[bh * 32768 + a_off16(m, k, 4)] = 0;
            g_kp[bh * 32768 + b_off16(k, m, 128)] = 0;
            g_vrow[bh * 32768 + m * 32 + (f & 31)] = 0;
        }
    }
}

// ---------------- LayerNorm -> A-perm bf16 ------------------------------------
__global__ void ln_kernel(const float* __restrict__ x,
                          const float* __restrict__ gamma,
                          const float* __restrict__ beta) {
    int row = blockIdx.x;
    int tid = threadIdx.x;
    const float4 v = ((const float4*)(x + (size_t)row * ND))[tid];
    __shared__ float red[4];

    float s = v.x + v.y + v.z + v.w;
#pragma unroll
    for (int o = 16; o; o >>= 1) s += __shfl_xor_sync(0xffffffffu, s, o);
    if ((tid & 31) == 0) red[tid >> 5] = s;
    __syncthreads();
    float mean = (red[0] + red[1] + red[2] + red[3]) * (1.0f / ND);
    __syncthreads();

    float a = v.x - mean, b = v.y - mean, c = v.z - mean, d = v.w - mean;
    float s2 = a * a + b * b + c * c + d * d;
#pragma unroll
    for (int o = 16; o; o >>= 1) s2 += __shfl_xor_sync(0xffffffffu, s2, o);
    if ((tid & 31) == 0) red[tid >> 5] = s2;
    __syncthreads();
    float var = (red[0] + red[1] + red[2] + red[3]) * (1.0f / ND);
    float inv = rsqrtf(var + 1e-5f);

    const float4 gg = ((const float4*)gamma)[tid];
    const float4 bt = ((const float4*)beta)[tid];
    float o0 = a * inv * gg.x + bt.x;
    float o1 = b * inv * gg.y + bt.y;
    float o2 = c * inv * gg.z + bt.z;
    float o3 = d * inv * gg.w + bt.w;
    int k0 = tid << 2;
    g_xnp[a_off16(row, k0, 32)] = bf2(o0, o1);
    g_xnp[a_off16(row, k0 + 2, 32)] = bf2(o2, o3);
}

// ---------------- streaming bf16 GEMM (no smem, no syncs) ---------------------
__global__ void __launch_bounds__(256) gemm2_kernel(
    const float* __restrict__ b0, const float* __restrict__ b1,
    const float* __restrict__ b2, const float* __restrict__ resid,
    float* __restrict__ Cf, int outproj) {
    const int tid = threadIdx.x, lane = tid & 31, warp = tid >> 5;
    const int wm = warp >> 2, wn = warp & 3, g = lane >> 2, tig = lane & 3;
    const int m0 = blockIdx.y * 64, n0 = blockIdx.x * 128;
    const int z = blockIdx.z;
    const int mode = outproj ? 1 : (z == 0 ? 0 : (z == 1 ? 2 : 3));
    const int widx = outproj ? 3 : z;
    const float* bias = outproj ? b0 : (z == 0 ? b0 : (z == 1 ? b1 : b2));
    const unsigned* Ap = outproj ? g_ctxp : g_xnp;
    const unsigned* Ab = Ap + (size_t)(((m0 + wm * 32) >> 4) * 32) * 128 + (lane << 2);
    const unsigned* Bb = g_wp + (size_t)widx * 131072 + (size_t)((n0 >> 3) + wn * 4) * 64 + (lane << 1);

    float4 acc[2][4] = {};
    uint4 a[2][2];
    uint2 b[2][4];
    a[0][0] = *(const uint4*)(Ab);
    a[0][1] = *(const uint4*)(Ab + 4096);
#pragma unroll
    for (int j = 0; j < 4; j++) b[0][j] = *(const uint2*)(Bb + j * 64);
#pragma unroll
    for (int kt = 0; kt < 32; kt++) {
        int cur = kt & 1, nxt = cur ^ 1;
        if (kt < 31) {
            a[nxt][0] = *(const uint4*)(Ab + (kt + 1) * 128);
            a[nxt][1] = *(const uint4*)(Ab + 4096 + (kt + 1) * 128);
#pragma unroll
            for (int j = 0; j < 4; j++)
                b[nxt][j] = *(const uint2*)(Bb + (size_t)(kt + 1) * 4096 + j * 64);
        }
#pragma unroll
        for (int j = 0; j < 4; j++) {
            mma16(acc[0][j], a[cur][0], b[cur][j]);
            mma16(acc[1][j], a[cur][1], b[cur][j]);
        }
    }

    const float KS = 0.125f * LOG2E;
#pragma unroll
    for (int i = 0; i < 2; i++)
#pragma unroll
        for (int j = 0; j < 4; j++) {
            int col = n0 + wn * 32 + j * 8 + (tig << 1);
            float2 bb = *(const float2*)&bias[col];
            float4 c = acc[i][j];
            float cx = c.x + bb.x, cy = c.y + bb.y;
            float cz = c.z + bb.x, cw = c.w + bb.y;
            int r0 = m0 + wm * 32 + i * 16 + g, r1 = r0 + 8;
            if (mode == 1) {
                size_t o0 = (size_t)r0 * ND + col, o1 = (size_t)r1 * ND + col;
                float2 rr0 = *(const float2*)&resid[o0];
                float2 rr1 = *(const float2*)&resid[o1];
                *(float2*)&Cf[o0] = make_float2(cx + rr0.x, cy + rr0.y);
                *(float2*)&Cf[o1] = make_float2(cz + rr1.x, cw + rr1.y);
            } else {
                int h = col >> 6, d = col & 63;
                int b0i = r0 / NL, l0 = r0 - b0i * NL;
                int b1i = r1 / NL, l1 = r1 - b1i * NL;
                int bh0 = b0i * NH + h, bh1 = b1i * NH + h;
                if (mode == 0) {
                    g_qp[bh0 * 32768 + a_off16(l0, d, 4)] = bf2(cx, cy);
                    g_qp[bh1 * 32768 + a_off16(l1, d, 4)] = bf2(cz, cw);
                } else if (mode == 2) {
                    g_kp[bh0 * 32768 + b_off16(d, l0, 128)] = bf2(cx * KS, cy * KS);
                    g_kp[bh1 * 32768 + b_off16(d, l1, 128)] = bf2(cz * KS, cw * KS);
                } else {
                    g_vrow[bh0 * 32768 + l0 * 32 + (d >> 1)] = bf2(cx, cy);
                    g_vrow[bh1 * 32768 + l1 * 32 + (d >> 1)] = bf2(cz, cw);
                }
            }
        }
}

// ---------------- flash attention: transposed conflict-free S2 ring -----------
// smem words: V 2x2048 | P 2048 | S2t [128 slots][72 stride] | redM | redS | m | l
#define OFF_V 0
#define OFF_P 4096
#define OFF_S2T 6144
#define S2STRIDE 72
#define OFF_RM 15360
#define OFF_RS 15872
#define OFF_M 16384
#define OFF_L 16448
#define ATTN_WORDS 16512
#define ATTN_SMEM_BYTES (ATTN_WORDS * 4)

__global__ void __launch_bounds__(256, 3) attn_kernel() {
    extern __shared__ float sm[];
    unsigned* Vs = (unsigned*)sm + OFF_V;
    unsigned* Ps = (unsigned*)sm + OFF_P;
    float* S2t = sm + OFF_S2T;     // [slot][row], addr = slot*72 + r
    float* redM = sm + OFF_RM;
    float* redS = sm + OFF_RS;
    float* row_m = sm + OFF_M;
    float* row_l = sm + OFF_L;

    const int it = blockIdx.x, bh = blockIdx.y;
    const int bq = bh >> 3, h = bh & 7;
    const int i0 = it << 6;
    const int tid = threadIdx.x;
    const int lane = tid & 31, warp = tid >> 5;
    const int g = lane >> 2, tig = lane & 3;
    const int c0 = (warp << 3) + (tig << 1);

    const unsigned* qpb = g_qp + bh * 32768;
    const unsigned* kpb = g_kp + bh * 32768;
    const unsigned* vrb = g_vrow + bh * 32768;

    if (tid < 64) { row_m[tid] = -1e30f; row_l[tid] = 0.f; }
    float4 O[4] = {};

    // warm the ring: band cols v in [0,64)  (one n8-tile per warp)
    {
        const int vt0 = warp << 3;
        const int nb = vt0 + 1000 - i0;
        float4 s2[4] = {};
#pragma unroll
        for (int kt = 0; kt < 4; kt++) {
            uint2 ba = *(const uint2*)(g_relp + (size_t)(kt * 272 + (nb >> 3)) * 64 + (lane << 1));
#pragma unroll
            for (int mt = 0; mt < 4; mt++) {
                uint4 afr = *(const uint4*)(qpb + (size_t)(((it << 2) + mt) * 4 + kt) * 128 + (lane << 2));
                mma16(s2[mt], afr, ba);
            }
        }
        int sl = vt0 + (tig << 1);
#pragma unroll
        for (int mt = 0; mt < 4; mt++) {
            int r0 = (mt << 4) + g, r1 = r0 + 8;
            S2t[sl * S2STRIDE + r0] = s2[mt].x;
            S2t[(sl + 1) * S2STRIDE + r0] = s2[mt].y;
            S2t[sl * S2STRIDE + r1] = s2[mt].z;
            S2t[(sl + 1) * S2STRIDE + r1] = s2[mt].w;
        }
    }

    for (int jt = 0; jt < 16; jt++) {
        const int j0 = jt << 6;
        unsigned* Vbuf = Vs + ((jt & 1) << 11);

        // stage V tile: row-major bf16 -> B-perm (pair over j via prmt)
#pragma unroll
        for (int i = 0; i < 4; i++) {
            int f = tid + (i << 8);
            int rp = f >> 5, c2 = f & 31;
            unsigned wa = vrb[(j0 + (rp << 1)) * 32 + c2];
            unsigned wb = vrb[(j0 + (rp << 1) + 1) * 32 + c2];
            Vbuf[b_off16(rp << 1, c2 << 1, 8)] = prmt(wa, wb, 0x5410);
            Vbuf[b_off16(rp << 1, (c2 << 1) + 1, 8)] = prmt(wa, wb, 0x7632);
        }

        // fused S1 + S2(ring, new 64 cols) mma: each Q fragment loaded once
        float4 s1[4];
        {
            const int vt = j0 + 64 + (warp << 3);
            const int na = vt + 1000 - i0;
            float4 s2a[4] = {};
#pragma unroll
            for (int mt = 0; mt < 4; mt++) s1[mt] = make_float4(0.f, 0.f, 0.f, 0.f);
#pragma unroll
            for (int kt = 0; kt < 4; kt++) {
                uint2 bk = *(const uint2*)(kpb + (size_t)(kt * 128 + (jt << 3) + warp) * 64 + (lane << 1));
                uint2 ba = *(const uint2*)(g_relp + (size_t)(kt * 272 + (na >> 3)) * 64 + (lane << 1));
#pragma unroll
                for (int mt = 0; mt < 4; mt++) {
                    uint4 afr = *(const uint4*)(qpb + (size_t)(((it << 2) + mt) * 4 + kt) * 128 + (lane << 2));
                    mma16(s1[mt], afr, bk);
                    mma16(s2a[mt], afr, ba);
                }
            }
            int sl = (vt & 127) + (tig << 1);
#pragma unroll
            for (int mt = 0; mt < 4; mt++) {
                int r0 = (mt << 4) + g, r1 = r0 + 8;
                S2t[sl * S2STRIDE + r0] = s2a[mt].x;
                S2t[(sl + 1) * S2STRIDE + r0] = s2a[mt].y;
                S2t[sl * S2STRIDE + r1] = s2a[mt].z;
                S2t[(sl + 1) * S2STRIDE + r1] = s2a[mt].w;
            }
        }
        __syncthreads();   // A: ring + V visible

        // phase A: gather S2 (conflict-free), mask, row-max partials
#pragma unroll
        for (int mt = 0; mt < 4; mt++) {
            int r0 = (mt << 4) + g, r1 = r0 + 8;
            int v0 = j0 + c0 - r0 + 63;
            int v1 = v0 - 8;
            s1[mt].x += S2t[(v0 & 127) * S2STRIDE + r0];
            s1[mt].y += S2t[((v0 + 1) & 127) * S2STRIDE + r0];
            s1[mt].z += S2t[(v1 & 127) * S2STRIDE + r1];
            s1[mt].w += S2t[((v1 + 1) & 127) * S2STRIDE + r1];
            if (j0 + c0 >= NL) { s1[mt].x = -1e30f; s1[mt].z = -1e30f; }
            if (j0 + c0 + 1 >= NL) { s1[mt].y = -1e30f; s1[mt].w = -1e30f; }
            float m0 = fmaxf(s1[mt].x, s1[mt].y);
            float m1 = fmaxf(s1[mt].z, s1[mt].w);
            m0 = fmaxf(m0, __shfl_xor_sync(0xffffffffu, m0, 1));
            m0 = fmaxf(m0, __shfl_xor_sync(0xffffffffu, m0, 2));
            m1 = fmaxf(m1, __shfl_xor_sync(0xffffffffu, m1, 1));
            m1 = fmaxf(m1, __shfl_xor_sync(0xffffffffu, m1, 2));
            if (tig == 0) {
                redM[(r0 << 3) + warp] = m0;
                redM[(r1 << 3) + warp] = m1;
            }
        }
        __syncthreads();   // B: row-max partials visible

        // phase B: mnew/alpha (local), exp, write P fragments, row-sum partials
        float al[4], ah[4];
#pragma unroll
        for (int mt = 0; mt < 4; mt++) {
            int r0 = (mt << 4) + g, r1 = r0 + 8;
            float4 p0 = *(float4*)&redM[r0 << 3];
            float4 p1 = *(float4*)&redM[(r0 << 3) + 4];
            float mp0 = fmaxf(fmaxf(fmaxf(p0.x, p0.y), fmaxf(p0.z, p0.w)),
                              fmaxf(fmaxf(p1.x, p1.y), fmaxf(p1.z, p1.w)));
            float4 q0 = *(float4*)&redM[r1 << 3];
            float4 q1 = *(float4*)&redM[(r1 << 3) + 4];
            float mp1 = fmaxf(fmaxf(fmaxf(q0.x, q0.y), fmaxf(q0.z, q0.w)),
                              fmaxf(fmaxf(q1.x, q1.y), fmaxf(q1.z, q1.w)));
            float mold0 = row_m[r0], mold1 = row_m[r1];
            float mn0 = fmaxf(mold0, mp0), mn1 = fmaxf(mold1, mp1);
            al[mt] = ex2f(mold0 - mn0);
            ah[mt] = ex2f(mold1 - mn1);
            float e00 = ex2f(s1[mt].x - mn0), e01 = ex2f(s1[mt].y - mn0);
            float e10 = ex2f(s1[mt].z - mn1), e11 = ex2f(s1[mt].w - mn1);
            Ps[a_off16(r0, c0, 4)] = bf2(e00, e01);
            Ps[a_off16(r1, c0, 4)] = bf2(e10, e11);
            float s0 = e00 + e01, sh = e10 + e11;
            s0 += __shfl_xor_sync(0xffffffffu, s0, 1);
            s0 += __shfl_xor_sync(0xffffffffu, s0, 2);
            sh += __shfl_xor_sync(0xffffffffu, sh, 1);
            sh += __shfl_xor_sync(0xffffffffu, sh, 2);
            if (tig == 0) {
                redS[(r0 << 3) + warp] = s0;
                redS[(r1 << 3) + warp] = sh;
            }
        }
        __syncthreads();   // C: P + sum partials visible

        // owner updates per-row softmax state
        if (tid < 64) {
            int i = tid;
            float4 p0 = *(float4*)&redM[i << 3];
            float4 p1 = *(float4*)&redM[(i << 3) + 4];
            float mp = fmaxf(fmaxf(fmaxf(p0.x, p0.y), fmaxf(p0.z, p0.w)),
                             fmaxf(fmaxf(p1.x, p1.y), fmaxf(p1.z, p1.w)));
            float mold = row_m[i];
            float mnew = fmaxf(mold, mp);
            float4 s0 = *(float4*)&redS[i << 3];
            float4 s1v = *(float4*)&redS[(i << 3) + 4];
            float ssum = s0.x + s0.y + s0.z + s0.w + s1v.x + s1v.y + s1v.z + s1v.w;
            row_l[i] = row_l[i] * ex2f(mold - mnew) + ssum;
            row_m[i] = mnew;
        }

        // rescale O (local alphas), then O += P @ V
#pragma unroll
        for (int mt = 0; mt < 4; mt++) {
            O[mt].x *= al[mt]; O[mt].y *= al[mt];
            O[mt].z *= ah[mt]; O[mt].w *= ah[mt];
        }
#pragma unroll
        for (int kt = 0; kt < 4; kt++) {
            uint2 bfr = *(uint2*)&Vbuf[((kt * 8 + warp) << 6) + (lane << 1)];
#pragma unroll
            for (int mt = 0; mt < 4; mt++) {
                uint4 afr = *(uint4*)&Ps[((mt * 4 + kt) << 7) + (lane << 2)];
                mma16(O[mt], afr, bfr);
            }
        }
    }

    __syncthreads();
    // normalize + write ctx as A-perm bf16
#pragma unroll
    for (int mt = 0; mt < 4; mt++) {
        int r0 = (mt << 4) + g, r1 = r0 + 8;
        int col = (warp << 3) + (tig << 1);
        if (i0 + r0 < NL) {
            float inv = 1.f / row_l[r0];
            int gm = bq * NL + i0 + r0;
            g_ctxp[a_off16(gm, (h << 6) + col, 32)] = bf2(O[mt].x * inv, O[mt].y * inv);
        }
        if (i0 + r1 < NL) {
            float inv = 1.f / row_l[r1];
            int gm = bq * NL + i0 + r1;
            g_ctxp[a_off16(gm, (h << 6) + col, 32)] = bf2(O[mt].z * inv, O[mt].w * inv);
        }
    }
}

// ---------------- launch ------------------------------------------------------
extern "C" void kernel_launch(void* const* d_in, const int* in_sizes, int n_in,
                              void* d_out, int out_size) {
    const float* x     = (const float*)d_in[0];
    const float* Wq    = (const float*)d_in[1];
    const float* bq    = (const float*)d_in[2];
    const float* Wk    = (const float*)d_in[3];
    const float* bk    = (const float*)d_in[4];
    const float* Wv    = (const float*)d_in[5];
    const float* bv    = (const float*)d_in[6];
    const float* Wo    = (const float*)d_in[7];
    const float* bo    = (const float*)d_in[8];
    const float* rel   = (const float*)d_in[9];
    const float* gamma = (const float*)d_in[10];
    const float* beta  = (const float*)d_in[11];
    float* out = (float*)d_out;

    cudaFuncSetAttribute(attn_kernel, cudaFuncAttributeMaxDynamicSharedMemorySize,
                         ATTN_SMEM_BYTES);

    prep_kernel<<<2384, 256>>>(Wq, Wk, Wv, Wo, rel);
    ln_kernel<<<8 * NL, 128>>>(x, gamma, beta);

    gemm2_kernel<<<dim3(4, 125, 3), 256>>>(bq, bk, bv, nullptr, nullptr, 0);  // QKV
    attn_kernel<<<dim3(16, NBH), 256, ATTN_SMEM_BYTES>>>();
    gemm2_kernel<<<dim3(4, 125, 1), 256>>>(bo, nullptr, nullptr, x, out, 1);  // out-proj
}

// round 11
// speedup vs baseline: 2.2856x; 1.3115x over previous
#include <cuda_runtime.h>
#include <cuda_bf16.h>

#define NL 1000
#define ND 512
#define NH 8
#define NDK 64
#define NRR 1999
#define NBH 64
#define LOG2E 1.4426950408889634f

// ---------------- device scratch: pre-permuted bf16 fragment arrays -----------
__device__ unsigned g_xnp [500 * 32 * 128];   // xn  A-perm (8000 x 512)
__device__ unsigned g_ctxp[500 * 32 * 128];   // ctx A-perm (8000 x 512)
__device__ unsigned g_wp  [4 * 131072];       // W   B-perm (512k x 512n) x4
__device__ unsigned g_qp  [NBH * 32768];      // q per bh: A-perm (1024 x 64)
__device__ unsigned g_kp  [NBH * 32768];      // k per bh: B-perm k=d, n=j (x0.125*log2e)
__device__ unsigned g_vrow[NBH * 32768];      // v per bh: row-major bf16 (1024 x 64)
__device__ unsigned g_relp[4 * 272 * 64];     // rel*log2e B-perm k=d, n=u_abs+64

// ---------------- helpers -----------------------------------------------------
__device__ __forceinline__ unsigned bf2(float lo, float hi) {
    unsigned r;
    asm("cvt.rn.bf16x2.f32 %0, %1, %2;" : "=r"(r) : "f"(hi), "f"(lo));
    return r;
}
__device__ __forceinline__ unsigned prmt(unsigned a, unsigned b, unsigned sel) {
    unsigned r;
    asm("prmt.b32 %0, %1, %2, %3;" : "=r"(r) : "r"(a), "r"(b), "r"(sel));
    return r;
}
__device__ __forceinline__ float ex2f(float x) {
    float r;
    asm("ex2.approx.ftz.f32 %0, %1;" : "=f"(r) : "f"(x));
    return r;
}
__device__ __forceinline__ void mma16(float4& d, uint4 a, uint2 b) {
    asm volatile(
        "mma.sync.aligned.m16n8k16.row.col.f32.bf16.bf16.f32 "
        "{%0,%1,%2,%3}, {%4,%5,%6,%7}, {%8,%9}, {%0,%1,%2,%3};\n"
        : "+f"(d.x), "+f"(d.y), "+f"(d.z), "+f"(d.w)
        : "r"(a.x), "r"(a.y), "r"(a.z), "r"(a.w), "r"(b.x), "r"(b.y));
}
__device__ __forceinline__ int a_off16(int m, int k, int nkt16) {
    return (((m >> 4) * nkt16 + (k >> 4)) << 7) +
           ((((m & 7) << 2) + ((k & 7) >> 1)) << 2) + ((m >> 3) & 1) + (((k >> 3) & 1) << 1);
}
__device__ __forceinline__ int b_off16(int k, int n, int nnt) {
    return (((k >> 4) * nnt + (n >> 3)) << 6) +
           ((((n & 7) << 2) + ((k & 7) >> 1)) << 1) + ((k >> 3) & 1);
}

// ---------------- fused preamble: wconv(4) + relconv + zfill ------------------
__global__ void prep_kernel(const float* __restrict__ W0, const float* __restrict__ W1,
                            const float* __restrict__ W2, const float* __restrict__ W3,
                            const float* __restrict__ rel) {
    int bid = blockIdx.x;
    if (bid < 2048) {
        int widx = bid >> 9;
        const float* W = (widx == 0) ? W0 : (widx == 1) ? W1 : (widx == 2) ? W2 : W3;
        int idx = ((bid & 511) << 8) + threadIdx.x;
        int n = idx >> 8, k = (idx & 255) << 1;
        g_wp[widx * 131072 + b_off16(k, n, 64)] =
            bf2(W[(size_t)n * ND + k], W[(size_t)n * ND + k + 1]);
    } else if (bid < 2320) {
        int idx = ((bid - 2048) << 8) + threadIdx.x;
        int u = idx >> 5, k = (idx & 31) << 1;
        int ua = u - 64;
        float a = 0.f, b = 0.f;
        if (ua >= 0 && ua < NRR) {
            a = rel[(size_t)ua * NDK + k] * LOG2E;
            b = rel[(size_t)ua * NDK + k + 1] * LOG2E;
        }
        g_relp[b_off16(k, u, 272)] = bf2(a, b);
    } else {
        int bh = bid - 2320;
        int t = threadIdx.x;
        for (int f = t; f < 768; f += 256) {
            int m = 1000 + (f >> 5);
            int k = (f & 31) << 1;
            g_qp[bh * 32768 + a_off16(m, k, 4)] = 0;
            g_kp[bh * 32768 + b_off16(k, m, 128)] = 0;
            g_vrow[bh * 32768 + m * 32 + (f & 31)] = 0;
        }
    }
}

// ---------------- LayerNorm -> A-perm bf16 ------------------------------------
__global__ void ln_kernel(const float* __restrict__ x,
                          const float* __restrict__ gamma,
                          const float* __restrict__ beta) {
    int row = blockIdx.x;
    int tid = threadIdx.x;
    const float4 v = ((const float4*)(x + (size_t)row * ND))[tid];
    __shared__ float red[4];

    float s = v.x + v.y + v.z + v.w;
#pragma unroll
    for (int o = 16; o; o >>= 1) s += __shfl_xor_sync(0xffffffffu, s, o);
    if ((tid & 31) == 0) red[tid >> 5] = s;
    __syncthreads();
    float mean = (red[0] + red[1] + red[2] + red[3]) * (1.0f / ND);
    __syncthreads();

    float a = v.x - mean, b = v.y - mean, c = v.z - mean, d = v.w - mean;
    float s2 = a * a + b * b + c * c + d * d;
#pragma unroll
    for (int o = 16; o; o >>= 1) s2 += __shfl_xor_sync(0xffffffffu, s2, o);
    if ((tid & 31) == 0) red[tid >> 5] = s2;
    __syncthreads();
    float var = (red[0] + red[1] + red[2] + red[3]) * (1.0f / ND);
    float inv = rsqrtf(var + 1e-5f);

    const float4 gg = ((const float4*)gamma)[tid];
    const float4 bt = ((const float4*)beta)[tid];
    float o0 = a * inv * gg.x + bt.x;
    float o1 = b * inv * gg.y + bt.y;
    float o2 = c * inv * gg.z + bt.z;
    float o3 = d * inv * gg.w + bt.w;
    int k0 = tid << 2;
    g_xnp[a_off16(row, k0, 32)] = bf2(o0, o1);
    g_xnp[a_off16(row, k0 + 2, 32)] = bf2(o2, o3);
}

// ---------------- streaming bf16 GEMM (no smem, no syncs) ---------------------
__global__ void __launch_bounds__(256) gemm2_kernel(
    const float* __restrict__ b0, const float* __restrict__ b1,
    const float* __restrict__ b2, const float* __restrict__ resid,
    float* __restrict__ Cf, int outproj) {
    const int tid = threadIdx.x, lane = tid & 31, warp = tid >> 5;
    const int wm = warp >> 2, wn = warp & 3, g = lane >> 2, tig = lane & 3;
    const int m0 = blockIdx.y * 64, n0 = blockIdx.x * 128;
    const int z = blockIdx.z;
    const int mode = outproj ? 1 : (z == 0 ? 0 : (z == 1 ? 2 : 3));
    const int widx = outproj ? 3 : z;
    const float* bias = outproj ? b0 : (z == 0 ? b0 : (z == 1 ? b1 : b2));
    const unsigned* Ap = outproj ? g_ctxp : g_xnp;
    const unsigned* Ab = Ap + (size_t)(((m0 + wm * 32) >> 4) * 32) * 128 + (lane << 2);
    const unsigned* Bb = g_wp + (size_t)widx * 131072 + (size_t)((n0 >> 3) + wn * 4) * 64 + (lane << 1);

    float4 acc[2][4] = {};
    uint4 a[2][2];
    uint2 b[2][4];
    a[0][0] = *(const uint4*)(Ab);
    a[0][1] = *(const uint4*)(Ab + 4096);
#pragma unroll
    for (int j = 0; j < 4; j++) b[0][j] = *(const uint2*)(Bb + j * 64);
#pragma unroll
    for (int kt = 0; kt < 32; kt++) {
        int cur = kt & 1, nxt = cur ^ 1;
        if (kt < 31) {
            a[nxt][0] = *(const uint4*)(Ab + (kt + 1) * 128);
            a[nxt][1] = *(const uint4*)(Ab + 4096 + (kt + 1) * 128);
#pragma unroll
            for (int j = 0; j < 4; j++)
                b[nxt][j] = *(const uint2*)(Bb + (size_t)(kt + 1) * 4096 + j * 64);
        }
#pragma unroll
        for (int j = 0; j < 4; j++) {
            mma16(acc[0][j], a[cur][0], b[cur][j]);
            mma16(acc[1][j], a[cur][1], b[cur][j]);
        }
    }

    const float KS = 0.125f * LOG2E;
#pragma unroll
    for (int i = 0; i < 2; i++)
#pragma unroll
        for (int j = 0; j < 4; j++) {
            int col = n0 + wn * 32 + j * 8 + (tig << 1);
            float2 bb = *(const float2*)&bias[col];
            float4 c = acc[i][j];
            float cx = c.x + bb.x, cy = c.y + bb.y;
            float cz = c.z + bb.x, cw = c.w + bb.y;
            int r0 = m0 + wm * 32 + i * 16 + g, r1 = r0 + 8;
            if (mode == 1) {
                size_t o0 = (size_t)r0 * ND + col, o1 = (size_t)r1 * ND + col;
                float2 rr0 = *(const float2*)&resid[o0];
                float2 rr1 = *(const float2*)&resid[o1];
                *(float2*)&Cf[o0] = make_float2(cx + rr0.x, cy + rr0.y);
                *(float2*)&Cf[o1] = make_float2(cz + rr1.x, cw + rr1.y);
            } else {
                int h = col >> 6, d = col & 63;
                int b0i = r0 / NL, l0 = r0 - b0i * NL;
                int b1i = r1 / NL, l1 = r1 - b1i * NL;
                int bh0 = b0i * NH + h, bh1 = b1i * NH + h;
                if (mode == 0) {
                    g_qp[bh0 * 32768 + a_off16(l0, d, 4)] = bf2(cx, cy);
                    g_qp[bh1 * 32768 + a_off16(l1, d, 4)] = bf2(cz, cw);
                } else if (mode == 2) {
                    g_kp[bh0 * 32768 + b_off16(d, l0, 128)] = bf2(cx * KS, cy * KS);
                    g_kp[bh1 * 32768 + b_off16(d, l1, 128)] = bf2(cz * KS, cw * KS);
                } else {
                    g_vrow[bh0 * 32768 + l0 * 32 + (d >> 1)] = bf2(cx, cy);
                    g_vrow[bh1 * 32768 + l1 * 32 + (d >> 1)] = bf2(cz, cw);
                }
            }
        }
}

// ---------------- flash attention: register-resident Q, 2mt x 2nt warp tile ---
// smem words: V 2x2048 | P 2048 | S2t [128][72] | redM 256 | redS 256 | m | l
#define OFF_V 0
#define OFF_P 4096
#define OFF_S2T 6144
#define S2STRIDE 72
#define OFF_RM 15360
#define OFF_RS 15616
#define OFF_M 15872
#define OFF_L 15936
#define ATTN_WORDS 16000
#define ATTN_SMEM_BYTES (ATTN_WORDS * 4)

__global__ void __launch_bounds__(256, 2) attn_kernel() {
    extern __shared__ float sm[];
    unsigned* Vs = (unsigned*)sm + OFF_V;
    unsigned* Ps = (unsigned*)sm + OFF_P;
    float* S2t = sm + OFF_S2T;     // [slot][row], addr = slot*72 + r
    float* redM = sm + OFF_RM;     // [64][4]
    float* redS = sm + OFF_RS;     // [64][4]
    float* row_m = sm + OFF_M;
    float* row_l = sm + OFF_L;

    const int it = blockIdx.x, bh = blockIdx.y;
    const int bq = bh >> 3, h = bh & 7;
    const int i0 = it << 6;
    const int tid = threadIdx.x;
    const int lane = tid & 31, warp = tid >> 5;
    const int wr = warp >> 2, wc = warp & 3;      // row half / col quarter
    const int g = lane >> 2, tig = lane & 3;

    const unsigned* qpb = g_qp + bh * 32768;
    const unsigned* kpb = g_kp + bh * 32768;
    const unsigned* vrb = g_vrow + bh * 32768;

    if (tid < 64) { row_m[tid] = -1e30f; row_l[tid] = 0.f; }

    // Q fragments register-resident for the whole kernel (2mt x 4kt)
    uint4 qf[2][4];
#pragma unroll
    for (int mt = 0; mt < 2; mt++)
#pragma unroll
        for (int kt = 0; kt < 4; kt++)
            qf[mt][kt] = *(const uint4*)(qpb +
                (size_t)(((it << 2) + (wr << 1) + mt) * 4 + kt) * 128 + (lane << 2));

    float4 O[2][2] = {};

    // warm the ring: band cols v in [0,64); warp covers 2 n8 col-tiles, its row half
#pragma unroll
    for (int nl = 0; nl < 2; nl++) {
        const int vt0 = ((wc << 1) + nl) << 3;
        const int nb8 = (vt0 + 1000 - i0) >> 3;
        float4 s2[2] = {};
#pragma unroll
        for (int kt = 0; kt < 4; kt++) {
            uint2 ba = *(const uint2*)(g_relp + (size_t)(kt * 272 + nb8) * 64 + (lane << 1));
#pragma unroll
            for (int mt = 0; mt < 2; mt++) mma16(s2[mt], qf[mt][kt], ba);
        }
        int sl = vt0 + (tig << 1);
#pragma unroll
        for (int mt = 0; mt < 2; mt++) {
            int r0 = (wr << 5) + (mt << 4) + g, r1 = r0 + 8;
            S2t[sl * S2STRIDE + r0] = s2[mt].x;
            S2t[(sl + 1) * S2STRIDE + r0] = s2[mt].y;
            S2t[sl * S2STRIDE + r1] = s2[mt].z;
            S2t[(sl + 1) * S2STRIDE + r1] = s2[mt].w;
        }
    }

    for (int jt = 0; jt < 16; jt++) {
        const int j0 = jt << 6;
        unsigned* Vbuf = Vs + ((jt & 1) << 11);

        // stage V tile: row-major bf16 -> B-perm (pair over j via prmt)
#pragma unroll
        for (int i = 0; i < 4; i++) {
            int f = tid + (i << 8);
            int rp = f >> 5, c2 = f & 31;
            unsigned wa = vrb[(j0 + (rp << 1)) * 32 + c2];
            unsigned wb = vrb[(j0 + (rp << 1) + 1) * 32 + c2];
            Vbuf[b_off16(rp << 1, c2 << 1, 8)] = prmt(wa, wb, 0x5410);
            Vbuf[b_off16(rp << 1, (c2 << 1) + 1, 8)] = prmt(wa, wb, 0x7632);
        }

        // fused S1 + S2(ring) mma from register-resident Q
        float4 s1[2][2] = {};
        {
            const int vt = j0 + 64 + ((wc << 1) << 3);     // first of 2 ring tiles
            const int na = (vt + 1000 - i0) >> 3;
            float4 s2a[2][2] = {};
#pragma unroll
            for (int kt = 0; kt < 4; kt++) {
                const unsigned* kb = kpb + (size_t)(kt * 128 + (jt << 3) + (wc << 1)) * 64 + (lane << 1);
                uint2 bk0 = *(const uint2*)(kb);
                uint2 bk1 = *(const uint2*)(kb + 64);
                const unsigned* rb = g_relp + (size_t)(kt * 272 + na) * 64 + (lane << 1);
                uint2 ba0 = *(const uint2*)(rb);
                uint2 ba1 = *(const uint2*)(rb + 64);
#pragma unroll
                for (int mt = 0; mt < 2; mt++) {
                    mma16(s1[mt][0], qf[mt][kt], bk0);
                    mma16(s1[mt][1], qf[mt][kt], bk1);
                    mma16(s2a[mt][0], qf[mt][kt], ba0);
                    mma16(s2a[mt][1], qf[mt][kt], ba1);
                }
            }
#pragma unroll
            for (int nl = 0; nl < 2; nl++) {
                int sl = ((vt + (nl << 3)) & 127) + (tig << 1);
#pragma unroll
                for (int mt = 0; mt < 2; mt++) {
                    int r0 = (wr << 5) + (mt << 4) + g, r1 = r0 + 8;
                    S2t[sl * S2STRIDE + r0] = s2a[mt][nl].x;
                    S2t[(sl + 1) * S2STRIDE + r0] = s2a[mt][nl].y;
                    S2t[sl * S2STRIDE + r1] = s2a[mt][nl].z;
                    S2t[(sl + 1) * S2STRIDE + r1] = s2a[mt][nl].w;
                }
            }
        }
        __syncthreads();   // A: ring + V visible

        // phase A: gather S2 (conflict-free), mask, row-max partials
#pragma unroll
        for (int mt = 0; mt < 2; mt++) {
            int r0 = (wr << 5) + (mt << 4) + g, r1 = r0 + 8;
            float m0 = -1e30f, m1 = -1e30f;
#pragma unroll
            for (int nl = 0; nl < 2; nl++) {
                int c0n = (wc << 4) + (nl << 3) + (tig << 1);
                int v0 = j0 + c0n - r0 + 63;
                s1[mt][nl].x += S2t[(v0 & 127) * S2STRIDE + r0];
                s1[mt][nl].y += S2t[((v0 + 1) & 127) * S2STRIDE + r0];
                s1[mt][nl].z += S2t[((v0 - 8) & 127) * S2STRIDE + r1];
                s1[mt][nl].w += S2t[((v0 - 7) & 127) * S2STRIDE + r1];
                if (j0 + c0n >= NL) { s1[mt][nl].x = -1e30f; s1[mt][nl].z = -1e30f; }
                if (j0 + c0n + 1 >= NL) { s1[mt][nl].y = -1e30f; s1[mt][nl].w = -1e30f; }
                m0 = fmaxf(m0, fmaxf(s1[mt][nl].x, s1[mt][nl].y));
                m1 = fmaxf(m1, fmaxf(s1[mt][nl].z, s1[mt][nl].w));
            }
            m0 = fmaxf(m0, __shfl_xor_sync(0xffffffffu, m0, 1));
            m0 = fmaxf(m0, __shfl_xor_sync(0xffffffffu, m0, 2));
            m1 = fmaxf(m1, __shfl_xor_sync(0xffffffffu, m1, 1));
            m1 = fmaxf(m1, __shfl_xor_sync(0xffffffffu, m1, 2));
            if (tig == 0) {
                redM[(r0 << 2) + wc] = m0;
                redM[(r1 << 2) + wc] = m1;
            }
        }
        __syncthreads();   // B: row-max partials visible

        // phase B: mnew/alpha (local), exp, write P fragments, row-sum partials
        float al[2], ah[2];
#pragma unroll
        for (int mt = 0; mt < 2; mt++) {
            int r0 = (wr << 5) + (mt << 4) + g, r1 = r0 + 8;
            float4 p0 = *(float4*)&redM[r0 << 2];
            float mp0 = fmaxf(fmaxf(p0.x, p0.y), fmaxf(p0.z, p0.w));
            float4 q0 = *(float4*)&redM[r1 << 2];
            float mp1 = fmaxf(fmaxf(q0.x, q0.y), fmaxf(q0.z, q0.w));
            float mold0 = row_m[r0], mold1 = row_m[r1];
            float mn0 = fmaxf(mold0, mp0), mn1 = fmaxf(mold1, mp1);
            al[mt] = ex2f(mold0 - mn0);
            ah[mt] = ex2f(mold1 - mn1);
            float s0 = 0.f, sh = 0.f;
#pragma unroll
            for (int nl = 0; nl < 2; nl++) {
                int c0n = (wc << 4) + (nl << 3) + (tig << 1);
                float e00 = ex2f(s1[mt][nl].x - mn0), e01 = ex2f(s1[mt][nl].y - mn0);
                float e10 = ex2f(s1[mt][nl].z - mn1), e11 = ex2f(s1[mt][nl].w - mn1);
                Ps[a_off16(r0, c0n, 4)] = bf2(e00, e01);
                Ps[a_off16(r1, c0n, 4)] = bf2(e10, e11);
                s0 += e00 + e01;
                sh += e10 + e11;
            }
            s0 += __shfl_xor_sync(0xffffffffu, s0, 1);
            s0 += __shfl_xor_sync(0xffffffffu, s0, 2);
            sh += __shfl_xor_sync(0xffffffffu, sh, 1);
            sh += __shfl_xor_sync(0xffffffffu, sh, 2);
            if (tig == 0) {
                redS[(r0 << 2) + wc] = s0;
                redS[(r1 << 2) + wc] = sh;
            }
        }
        __syncthreads();   // C: P + sum partials visible

        // owner updates per-row softmax state
        if (tid < 64) {
            int i = tid;
            float4 p0 = *(float4*)&redM[i << 2];
            float mp = fmaxf(fmaxf(p0.x, p0.y), fmaxf(p0.z, p0.w));
            float mold = row_m[i];
            float mnew = fmaxf(mold, mp);
            float4 s0 = *(float4*)&redS[i << 2];
            row_l[i] = row_l[i] * ex2f(mold - mnew) + (s0.x + s0.y + s0.z + s0.w);
            row_m[i] = mnew;
        }

        // rescale O (local alphas), then O += P @ V
#pragma unroll
        for (int mt = 0; mt < 2; mt++)
#pragma unroll
            for (int nl = 0; nl < 2; nl++) {
                O[mt][nl].x *= al[mt]; O[mt][nl].y *= al[mt];
                O[mt][nl].z *= ah[mt]; O[mt][nl].w *= ah[mt];
            }
#pragma unroll
        for (int kt = 0; kt < 4; kt++) {
            uint2 bv0 = *(uint2*)&Vbuf[((kt * 8 + (wc << 1)) << 6) + (lane << 1)];
            uint2 bv1 = *(uint2*)&Vbuf[((kt * 8 + (wc << 1) + 1) << 6) + (lane << 1)];
#pragma unroll
            for (int mt = 0; mt < 2; mt++) {
                uint4 afr = *(uint4*)&Ps[((((wr << 1) + mt) * 4 + kt) << 7) + (lane << 2)];
                mma16(O[mt][0], afr, bv0);
                mma16(O[mt][1], afr, bv1);
            }
        }
    }

    __syncthreads();
    // normalize + write ctx as A-perm bf16
#pragma unroll
    for (int mt = 0; mt < 2; mt++)
#pragma unroll
        for (int nl = 0; nl < 2; nl++) {
            int r0 = (wr << 5) + (mt << 4) + g, r1 = r0 + 8;
            int col = (wc << 4) + (nl << 3) + (tig << 1);
            if (i0 + r0 < NL) {
                float inv = 1.f / row_l[r0];
                int gm = bq * NL + i0 + r0;
                g_ctxp[a_off16(gm, (h << 6) + col, 32)] =
                    bf2(O[mt][nl].x * inv, O[mt][nl].y * inv);
            }
            if (i0 + r1 < NL) {
                float inv = 1.f / row_l[r1];
                int gm = bq * NL + i0 + r1;
                g_ctxp[a_off16(gm, (h << 6) + col, 32)] =
                    bf2(O[mt][nl].z * inv, O[mt][nl].w * inv);
            }
        }
}

// ---------------- launch ------------------------------------------------------
extern "C" void kernel_launch(void* const* d_in, const int* in_sizes, int n_in,
                              void* d_out, int out_size) {
    const float* x     = (const float*)d_in[0];
    const float* Wq    = (const float*)d_in[1];
    const float* bq    = (const float*)d_in[2];
    const float* Wk    = (const float*)d_in[3];
    const float* bk    = (const float*)d_in[4];
    const float* Wv    = (const float*)d_in[5];
    const float* bv    = (const float*)d_in[6];
    const float* Wo    = (const float*)d_in[7];
    const float* bo    = (const float*)d_in[8];
    const float* rel   = (const float*)d_in[9];
    const float* gamma = (const float*)d_in[10];
    const float* beta  = (const float*)d_in[11];
    float* out = (float*)d_out;

    cudaFuncSetAttribute(attn_kernel, cudaFuncAttributeMaxDynamicSharedMemorySize,
                         ATTN_SMEM_BYTES);

    prep_kernel<<<2384, 256>>>(Wq, Wk, Wv, Wo, rel);
    ln_kernel<<<8 * NL, 128>>>(x, gamma, beta);

    gemm2_kernel<<<dim3(4, 125, 3), 256>>>(bq, bk, bv, nullptr, nullptr, 0);  // QKV
    attn_kernel<<<dim3(16, NBH), 256, ATTN_SMEM_BYTES>>>();
    gemm2_kernel<<<dim3(4, 125, 1), 256>>>(bo, nullptr, nullptr, x, out, 1);  // out-proj
}

// round 12
// speedup vs baseline: 2.6438x; 1.1567x over previous
#include <cuda_runtime.h>
#include <cuda_bf16.h>

#define NL 1000
#define ND 512
#define NH 8
#define NDK 64
#define NRR 1999
#define NBH 64
#define LOG2E 1.4426950408889634f

// ---------------- device scratch: pre-permuted bf16 fragment arrays -----------
__device__ unsigned g_xnp [500 * 32 * 128];   // xn  A-perm (8000 x 512)
__device__ unsigned g_ctxp[500 * 32 * 128];   // ctx A-perm (8000 x 512)
__device__ unsigned g_wp  [4 * 131072];       // W   B-perm (512k x 512n) x4
__device__ unsigned g_qp  [NBH * 32768];      // q per bh: A-perm (1024 x 64)
__device__ unsigned g_kp  [NBH * 32768];      // k per bh: B-perm k=d, n=j (x0.125*log2e)
__device__ unsigned g_vrow[NBH * 32768];      // v per bh: row-major bf16 (1024 x 64)
__device__ unsigned g_vperm[NBH * 32768];     // v per bh: B-perm k=j(1024), n=d(64)
__device__ unsigned g_relp[4 * 272 * 64];     // rel*log2e B-perm k=d, n=u_abs+64

// ---------------- helpers -----------------------------------------------------
__device__ __forceinline__ unsigned bf2(float lo, float hi) {
    unsigned r;
    asm("cvt.rn.bf16x2.f32 %0, %1, %2;" : "=r"(r) : "f"(hi), "f"(lo));
    return r;
}
__device__ __forceinline__ unsigned prmt(unsigned a, unsigned b, unsigned sel) {
    unsigned r;
    asm("prmt.b32 %0, %1, %2, %3;" : "=r"(r) : "r"(a), "r"(b), "r"(sel));
    return r;
}
__device__ __forceinline__ float ex2f(float x) {
    float r;
    asm("ex2.approx.ftz.f32 %0, %1;" : "=f"(r) : "f"(x));
    return r;
}
__device__ __forceinline__ void mma16(float4& d, uint4 a, uint2 b) {
    asm volatile(
        "mma.sync.aligned.m16n8k16.row.col.f32.bf16.bf16.f32 "
        "{%0,%1,%2,%3}, {%4,%5,%6,%7}, {%8,%9}, {%0,%1,%2,%3};\n"
        : "+f"(d.x), "+f"(d.y), "+f"(d.z), "+f"(d.w)
        : "r"(a.x), "r"(a.y), "r"(a.z), "r"(a.w), "r"(b.x), "r"(b.y));
}
__device__ __forceinline__ int a_off16(int m, int k, int nkt16) {
    return (((m >> 4) * nkt16 + (k >> 4)) << 7) +
           ((((m & 7) << 2) + ((k & 7) >> 1)) << 2) + ((m >> 3) & 1) + (((k >> 3) & 1) << 1);
}
__device__ __forceinline__ int b_off16(int k, int n, int nnt) {
    return (((k >> 4) * nnt + (n >> 3)) << 6) +
           ((((n & 7) << 2) + ((k & 7) >> 1)) << 1) + ((k >> 3) & 1);
}

// ---------------- fused preamble: wconv(4) + relconv + zfill ------------------
__global__ void prep_kernel(const float* __restrict__ W0, const float* __restrict__ W1,
                            const float* __restrict__ W2, const float* __restrict__ W3,
                            const float* __restrict__ rel) {
    int bid = blockIdx.x;
    if (bid < 2048) {
        int widx = bid >> 9;
        const float* W = (widx == 0) ? W0 : (widx == 1) ? W1 : (widx == 2) ? W2 : W3;
        int idx = ((bid & 511) << 8) + threadIdx.x;
        int n = idx >> 8, k = (idx & 255) << 1;
        g_wp[widx * 131072 + b_off16(k, n, 64)] =
            bf2(W[(size_t)n * ND + k], W[(size_t)n * ND + k + 1]);
    } else if (bid < 2320) {
        int idx = ((bid - 2048) << 8) + threadIdx.x;
        int u = idx >> 5, k = (idx & 31) << 1;
        int ua = u - 64;
        float a = 0.f, b = 0.f;
        if (ua >= 0 && ua < NRR) {
            a = rel[(size_t)ua * NDK + k] * LOG2E;
            b = rel[(size_t)ua * NDK + k + 1] * LOG2E;
        }
        g_relp[b_off16(k, u, 272)] = bf2(a, b);
    } else {
        int bh = bid - 2320;
        int t = threadIdx.x;
        for (int f = t; f < 768; f += 256) {
            int m = 1000 + (f >> 5);
            int k = (f & 31) << 1;
            g_qp[bh * 32768 + a_off16(m, k, 4)] = 0;
            g_kp[bh * 32768 + b_off16(k, m, 128)] = 0;
            g_vrow[bh * 32768 + m * 32 + (f & 31)] = 0;
        }
    }
}

// ---------------- LayerNorm -> A-perm bf16 ------------------------------------
__global__ void ln_kernel(const float* __restrict__ x,
                          const float* __restrict__ gamma,
                          const float* __restrict__ beta) {
    int row = blockIdx.x;
    int tid = threadIdx.x;
    const float4 v = ((const float4*)(x + (size_t)row * ND))[tid];
    __shared__ float red[4];

    float s = v.x + v.y + v.z + v.w;
#pragma unroll
    for (int o = 16; o; o >>= 1) s += __shfl_xor_sync(0xffffffffu, s, o);
    if ((tid & 31) == 0) red[tid >> 5] = s;
    __syncthreads();
    float mean = (red[0] + red[1] + red[2] + red[3]) * (1.0f / ND);
    __syncthreads();

    float a = v.x - mean, b = v.y - mean, c = v.z - mean, d = v.w - mean;
    float s2 = a * a + b * b + c * c + d * d;
#pragma unroll
    for (int o = 16; o; o >>= 1) s2 += __shfl_xor_sync(0xffffffffu, s2, o);
    if ((tid & 31) == 0) red[tid >> 5] = s2;
    __syncthreads();
    float var = (red[0] + red[1] + red[2] + red[3]) * (1.0f / ND);
    float inv = rsqrtf(var + 1e-5f);

    const float4 gg = ((const float4*)gamma)[tid];
    const float4 bt = ((const float4*)beta)[tid];
    float o0 = a * inv * gg.x + bt.x;
    float o1 = b * inv * gg.y + bt.y;
    float o2 = c * inv * gg.z + bt.z;
    float o3 = d * inv * gg.w + bt.w;
    int k0 = tid << 2;
    g_xnp[a_off16(row, k0, 32)] = bf2(o0, o1);
    g_xnp[a_off16(row, k0 + 2, 32)] = bf2(o2, o3);
}

// ---------------- V row-major -> B-perm global (pair over j via prmt) ---------
__global__ void vperm_kernel() {
    int idx = blockIdx.x * 256 + threadIdx.x;   // 1048576 = 64 bh x 512 rp x 32 c2
    int bh = idx >> 14;
    int r = (idx >> 5) & 511;
    int c2 = idx & 31;
    const unsigned* vb = g_vrow + bh * 32768;
    unsigned wa = vb[(r << 1) * 32 + c2];
    unsigned wb = vb[((r << 1) + 1) * 32 + c2];
    unsigned* vp = g_vperm + bh * 32768;
    vp[b_off16(r << 1, c2 << 1, 8)] = prmt(wa, wb, 0x5410);
    vp[b_off16(r << 1, (c2 << 1) + 1, 8)] = prmt(wa, wb, 0x7632);
}

// ---------------- streaming bf16 GEMM (no smem, no syncs) ---------------------
__global__ void __launch_bounds__(256) gemm2_kernel(
    const float* __restrict__ b0, const float* __restrict__ b1,
    const float* __restrict__ b2, const float* __restrict__ resid,
    float* __restrict__ Cf, int outproj) {
    const int tid = threadIdx.x, lane = tid & 31, warp = tid >> 5;
    const int wm = warp >> 2, wn = warp & 3, g = lane >> 2, tig = lane & 3;
    const int m0 = blockIdx.y * 64, n0 = blockIdx.x * 128;
    const int z = blockIdx.z;
    const int mode = outproj ? 1 : (z == 0 ? 0 : (z == 1 ? 2 : 3));
    const int widx = outproj ? 3 : z;
    const float* bias = outproj ? b0 : (z == 0 ? b0 : (z == 1 ? b1 : b2));
    const unsigned* Ap = outproj ? g_ctxp : g_xnp;
    const unsigned* Ab = Ap + (size_t)(((m0 + wm * 32) >> 4) * 32) * 128 + (lane << 2);
    const unsigned* Bb = g_wp + (size_t)widx * 131072 + (size_t)((n0 >> 3) + wn * 4) * 64 + (lane << 1);

    float4 acc[2][4] = {};
    uint4 a[2][2];
    uint2 b[2][4];
    a[0][0] = *(const uint4*)(Ab);
    a[0][1] = *(const uint4*)(Ab + 4096);
#pragma unroll
    for (int j = 0; j < 4; j++) b[0][j] = *(const uint2*)(Bb + j * 64);
#pragma unroll
    for (int kt = 0; kt < 32; kt++) {
        int cur = kt & 1, nxt = cur ^ 1;
        if (kt < 31) {
            a[nxt][0] = *(const uint4*)(Ab + (kt + 1) * 128);
            a[nxt][1] = *(const uint4*)(Ab + 4096 + (kt + 1) * 128);
#pragma unroll
            for (int j = 0; j < 4; j++)
                b[nxt][j] = *(const uint2*)(Bb + (size_t)(kt + 1) * 4096 + j * 64);
        }
#pragma unroll
        for (int j = 0; j < 4; j++) {
            mma16(acc[0][j], a[cur][0], b[cur][j]);
            mma16(acc[1][j], a[cur][1], b[cur][j]);
        }
    }

    const float KS = 0.125f * LOG2E;
#pragma unroll
    for (int i = 0; i < 2; i++)
#pragma unroll
        for (int j = 0; j < 4; j++) {
            int col = n0 + wn * 32 + j * 8 + (tig << 1);
            float2 bb = *(const float2*)&bias[col];
            float4 c = acc[i][j];
            float cx = c.x + bb.x, cy = c.y + bb.y;
            float cz = c.z + bb.x, cw = c.w + bb.y;
            int r0 = m0 + wm * 32 + i * 16 + g, r1 = r0 + 8;
            if (mode == 1) {
                size_t o0 = (size_t)r0 * ND + col, o1 = (size_t)r1 * ND + col;
                float2 rr0 = *(const float2*)&resid[o0];
                float2 rr1 = *(const float2*)&resid[o1];
                *(float2*)&Cf[o0] = make_float2(cx + rr0.x, cy + rr0.y);
                *(float2*)&Cf[o1] = make_float2(cz + rr1.x, cw + rr1.y);
            } else {
                int h = col >> 6, d = col & 63;
                int b0i = r0 / NL, l0 = r0 - b0i * NL;
                int b1i = r1 / NL, l1 = r1 - b1i * NL;
                int bh0 = b0i * NH + h, bh1 = b1i * NH + h;
                if (mode == 0) {
                    g_qp[bh0 * 32768 + a_off16(l0, d, 4)] = bf2(cx, cy);
                    g_qp[bh1 * 32768 + a_off16(l1, d, 4)] = bf2(cz, cw);
                } else if (mode == 2) {
                    g_kp[bh0 * 32768 + b_off16(d, l0, 128)] = bf2(cx * KS, cy * KS);
                    g_kp[bh1 * 32768 + b_off16(d, l1, 128)] = bf2(cz * KS, cw * KS);
                } else {
                    g_vrow[bh0 * 32768 + l0 * 32 + (d >> 1)] = bf2(cx, cy);
                    g_vrow[bh1 * 32768 + l1 * 32 + (d >> 1)] = bf2(cz, cw);
                }
            }
        }
}

// ---------------- flash attention: warp-exclusive rows, fully async -----------
// 128 threads = 4 warps; warp owns rows [w*16, w*16+16) x all 64 cols.
// Per-warp private S2 ring [128 slots][stride 19]. No __syncthreads in loop.
#define S2STRIDE 19

__global__ void __launch_bounds__(128) attn_kernel() {
    __shared__ float S2all[4 * 128 * S2STRIDE];

    const int it = blockIdx.x, bh = blockIdx.y;
    const int bq = bh >> 3, h = bh & 7;
    const int i0 = it << 6;
    const int tid = threadIdx.x;
    const int lane = tid & 31, w = tid >> 5;
    const int g = lane >> 2, tig = lane & 3;
    float* S2w = S2all + w * 128 * S2STRIDE;

    const unsigned* qpb = g_qp + bh * 32768;
    const unsigned* kpb = g_kp + bh * 32768;
    const unsigned* vpb = g_vperm + bh * 32768;

    // Q fragments register-resident: A-tile (it*4 + w), 4 kt tiles
    uint4 qf[4];
#pragma unroll
    for (int kt = 0; kt < 4; kt++)
        qf[kt] = *(const uint4*)(qpb + (size_t)(((it << 2) + w) * 4 + kt) * 128 + (lane << 2));

    float rm0 = -1e30f, rm1 = -1e30f, rl0 = 0.f, rl1 = 0.f;
    float4 O[8] = {};

    // relp n8 index = v8_tile + nboff  (v = j - r_local + 15, r_local in [0,16) of this warp)
    const int nboff = (1048 - i0 - (w << 4)) >> 3;

    // warm the ring: v in [0, 80) -> 10 v8-tiles
#pragma unroll
    for (int vt = 0; vt < 10; vt++) {
        float4 a = make_float4(0.f, 0.f, 0.f, 0.f);
        const unsigned* rb = g_relp + (size_t)(vt + nboff) * 64 + (lane << 1);
#pragma unroll
        for (int kt = 0; kt < 4; kt++)
            mma16(a, qf[kt], *(const uint2*)(rb + (size_t)kt * 272 * 64));
        int sl = (vt << 3) + (tig << 1);
        S2w[sl * S2STRIDE + g] = a.x;
        S2w[(sl + 1) * S2STRIDE + g] = a.y;
        S2w[sl * S2STRIDE + g + 8] = a.z;
        S2w[(sl + 1) * S2STRIDE + g + 8] = a.w;
    }
    __syncwarp();

    for (int jt = 0; jt < 16; jt++) {
        const int j0 = jt << 6;

        // S2: compute new band tiles v in [j0+16, j0+80) into the ring
#pragma unroll
        for (int vt = 0; vt < 8; vt++) {
            int v8 = ((j0 + 16) >> 3) + vt;
            float4 a = make_float4(0.f, 0.f, 0.f, 0.f);
            const unsigned* rb = g_relp + (size_t)(v8 + nboff) * 64 + (lane << 1);
#pragma unroll
            for (int kt = 0; kt < 4; kt++)
                mma16(a, qf[kt], *(const uint2*)(rb + (size_t)kt * 272 * 64));
            int sl = ((j0 + 16 + (vt << 3)) & 127) + (tig << 1);
            S2w[sl * S2STRIDE + g] = a.x;
            S2w[(sl + 1) * S2STRIDE + g] = a.y;
            S2w[sl * S2STRIDE + g + 8] = a.z;
            S2w[(sl + 1) * S2STRIDE + g + 8] = a.w;
        }
        __syncwarp();

        // S1 = Q @ K^T over all 8 n8 tiles
        float4 s1[8] = {};
#pragma unroll
        for (int kt = 0; kt < 4; kt++) {
            const unsigned* kb = kpb + (size_t)(kt * 128 + (j0 >> 3)) * 64 + (lane << 1);
#pragma unroll
            for (int nt = 0; nt < 8; nt++)
                mma16(s1[nt], qf[kt], *(const uint2*)(kb + (nt << 6)));
        }

        // gather ring + mask + row max (warp-local)
        float m0 = -1e30f, m1 = -1e30f;
#pragma unroll
        for (int nt = 0; nt < 8; nt++) {
            int c = (nt << 3) + (tig << 1);
            int v0 = j0 + c - g + 15;
            int v1 = v0 - 8;
            s1[nt].x += S2w[(v0 & 127) * S2STRIDE + g];
            s1[nt].y += S2w[((v0 + 1) & 127) * S2STRIDE + g];
            s1[nt].z += S2w[(v1 & 127) * S2STRIDE + g + 8];
            s1[nt].w += S2w[((v1 + 1) & 127) * S2STRIDE + g + 8];
            if (j0 + c >= NL) { s1[nt].x = -1e30f; s1[nt].z = -1e30f; }
            if (j0 + c + 1 >= NL) { s1[nt].y = -1e30f; s1[nt].w = -1e30f; }
            m0 = fmaxf(m0, fmaxf(s1[nt].x, s1[nt].y));
            m1 = fmaxf(m1, fmaxf(s1[nt].z, s1[nt].w));
        }
        m0 = fmaxf(m0, __shfl_xor_sync(0xffffffffu, m0, 1));
        m0 = fmaxf(m0, __shfl_xor_sync(0xffffffffu, m0, 2));
        m1 = fmaxf(m1, __shfl_xor_sync(0xffffffffu, m1, 1));
        m1 = fmaxf(m1, __shfl_xor_sync(0xffffffffu, m1, 2));

        float mn0 = fmaxf(rm0, m0), mn1 = fmaxf(rm1, m1);
        float a0 = ex2f(rm0 - mn0), a1 = ex2f(rm1 - mn1);
        rm0 = mn0; rm1 = mn1;

        // exp -> P fragments in registers, row sums
        unsigned plo[8], phi[8];
        float s0 = 0.f, sh = 0.f;
#pragma unroll
        for (int nt = 0; nt < 8; nt++) {
            float e00 = ex2f(s1[nt].x - mn0), e01 = ex2f(s1[nt].y - mn0);
            float e10 = ex2f(s1[nt].z - mn1), e11 = ex2f(s1[nt].w - mn1);
            plo[nt] = bf2(e00, e01);
            phi[nt] = bf2(e10, e11);
            s0 += e00 + e01;
            sh += e10 + e11;
        }
        s0 += __shfl_xor_sync(0xffffffffu, s0, 1);
        s0 += __shfl_xor_sync(0xffffffffu, s0, 2);
        sh += __shfl_xor_sync(0xffffffffu, sh, 1);
        sh += __shfl_xor_sync(0xffffffffu, sh, 2);
        rl0 = rl0 * a0 + s0;
        rl1 = rl1 * a1 + sh;

        // O rescale, then O += P @ V (P from registers, V frags from global)
#pragma unroll
        for (int dnt = 0; dnt < 8; dnt++) {
            O[dnt].x *= a0; O[dnt].y *= a0;
            O[dnt].z *= a1; O[dnt].w *= a1;
        }
#pragma unroll
        for (int kt = 0; kt < 4; kt++) {
            uint4 pa = make_uint4(plo[2 * kt], phi[2 * kt], plo[2 * kt + 1], phi[2 * kt + 1]);
            const unsigned* vb2 = vpb + (size_t)((((j0 >> 4) + kt) * 8) << 6) + (lane << 1);
#pragma unroll
            for (int dnt = 0; dnt < 8; dnt++)
                mma16(O[dnt], pa, *(const uint2*)(vb2 + (dnt << 6)));
        }
        __syncwarp();   // ring reads done before next tile's ring writes
    }

    // normalize + write ctx as A-perm bf16
    float inv0 = 1.f / rl0, inv1 = 1.f / rl1;
    int r0g = i0 + (w << 4) + g, r1g = r0g + 8;
#pragma unroll
    for (int dnt = 0; dnt < 8; dnt++) {
        int col = (h << 6) + (dnt << 3) + (tig << 1);
        if (r0g < NL)
            g_ctxp[a_off16(bq * NL + r0g, col, 32)] = bf2(O[dnt].x * inv0, O[dnt].y * inv0);
        if (r1g < NL)
            g_ctxp[a_off16(bq * NL + r1g, col, 32)] = bf2(O[dnt].z * inv1, O[dnt].w * inv1);
    }
}

// ---------------- launch ------------------------------------------------------
extern "C" void kernel_launch(void* const* d_in, const int* in_sizes, int n_in,
                              void* d_out, int out_size) {
    const float* x     = (const float*)d_in[0];
    const float* Wq    = (const float*)d_in[1];
    const float* bq    = (const float*)d_in[2];
    const float* Wk    = (const float*)d_in[3];
    const float* bk    = (const float*)d_in[4];
    const float* Wv    = (const float*)d_in[5];
    const float* bv    = (const float*)d_in[6];
    const float* Wo    = (const float*)d_in[7];
    const float* bo    = (const float*)d_in[8];
    const float* rel   = (const float*)d_in[9];
    const float* gamma = (const float*)d_in[10];
    const float* beta  = (const float*)d_in[11];
    float* out = (float*)d_out;

    prep_kernel<<<2384, 256>>>(Wq, Wk, Wv, Wo, rel);
    ln_kernel<<<8 * NL, 128>>>(x, gamma, beta);

    gemm2_kernel<<<dim3(4, 125, 3), 256>>>(bq, bk, bv, nullptr, nullptr, 0);  // QKV
    vperm_kernel<<<4096, 256>>>();
    attn_kernel<<<dim3(16, NBH), 128>>>();
    gemm2_kernel<<<dim3(4, 125, 1), 256>>>(bo, nullptr, nullptr, x, out, 1);  // out-proj
}

// round 13
// speedup vs baseline: 3.1396x; 1.1875x over previous
#include <cuda_runtime.h>
#include <cuda_bf16.h>

#define NL 1000
#define ND 512
#define NH 8
#define NDK 64
#define NRR 1999
#define NBH 64
#define LOG2E 1.4426950408889634f

// ---------------- device scratch: pre-permuted bf16 fragment arrays -----------
__device__ unsigned g_xnp [500 * 32 * 128];   // xn  A-perm (8000 x 512)
__device__ unsigned g_ctxp[500 * 32 * 128];   // ctx A-perm (8000 x 512)
__device__ unsigned g_wp  [4 * 131072];       // W   B-perm (512k x 512n) x4
__device__ unsigned g_qp  [NBH * 32768];      // q per bh: A-perm (1024 x 64)
__device__ unsigned g_kp  [NBH * 32768];      // k per bh: pair-packed B (k=d, n=j)
__device__ unsigned g_vp  [NBH * 32768];      // v per bh: pair-packed B (k=j, n=d)
__device__ unsigned g_relp[4 * 136 * 128];    // rel*log2e pair-packed B (k=d, n=u+72)

// ---------------- helpers -----------------------------------------------------
__device__ __forceinline__ unsigned bf2(float lo, float hi) {
    unsigned r;
    asm("cvt.rn.bf16x2.f32 %0, %1, %2;" : "=r"(r) : "f"(hi), "f"(lo));
    return r;
}
__device__ __forceinline__ float ex2f(float x) {
    float r;
    asm("ex2.approx.ftz.f32 %0, %1;" : "=f"(r) : "f"(x));
    return r;
}
__device__ __forceinline__ void mma16(float4& d, uint4 a, uint2 b) {
    asm volatile(
        "mma.sync.aligned.m16n8k16.row.col.f32.bf16.bf16.f32 "
        "{%0,%1,%2,%3}, {%4,%5,%6,%7}, {%8,%9}, {%0,%1,%2,%3};\n"
        : "+f"(d.x), "+f"(d.y), "+f"(d.z), "+f"(d.w)
        : "r"(a.x), "r"(a.y), "r"(a.z), "r"(a.w), "r"(b.x), "r"(b.y));
}
// A tile 16x16 (u32 = bf16x2 over k)
__device__ __forceinline__ int a_off16(int m, int k, int nkt16) {
    return (((m >> 4) * nkt16 + (k >> 4)) << 7) +
           ((((m & 7) << 2) + ((k & 7) >> 1)) << 2) + ((m >> 3) & 1) + (((k >> 3) & 1) << 1);
}
// classic B tile 16x8 (for g_wp only)
__device__ __forceinline__ int b_off16(int k, int n, int nnt) {
    return (((k >> 4) * nnt + (n >> 3)) << 6) +
           ((((n & 7) << 2) + ((k & 7) >> 1)) << 1) + ((k >> 3) & 1);
}
// pair-packed B: two n8 tiles per 128-word block, per-lane 4 words
// word = pairblk*128 + lane*4 + nl*2 + khalf
__device__ __forceinline__ int bp_off(int k, int n, int NP) {
    return (((k >> 4) * NP + (n >> 4)) << 7) +
           ((((n & 7) << 2) + ((k & 7) >> 1)) << 2) + (((n >> 3) & 1) << 1) + ((k >> 3) & 1);
}

// ---------------- fused preamble: wconv(4) + relconv + zfill + layernorm ------
__global__ void prep_kernel(const float* __restrict__ W0, const float* __restrict__ W1,
                            const float* __restrict__ W2, const float* __restrict__ W3,
                            const float* __restrict__ rel,
                            const float* __restrict__ x,
                            const float* __restrict__ gamma,
                            const float* __restrict__ beta) {
    __shared__ float red[8];
    int bid = blockIdx.x;
    if (bid < 2048) {
        int widx = bid >> 9;
        const float* W = (widx == 0) ? W0 : (widx == 1) ? W1 : (widx == 2) ? W2 : W3;
        int idx = ((bid & 511) << 8) + threadIdx.x;
        int n = idx >> 8, k = (idx & 255) << 1;
        g_wp[widx * 131072 + b_off16(k, n, 64)] =
            bf2(W[(size_t)n * ND + k], W[(size_t)n * ND + k + 1]);
    } else if (bid < 2320) {
        // rel * log2e -> pair-packed B, n = u_abs + 72
        int idx = ((bid - 2048) << 8) + threadIdx.x;     // 69632 words
        int u = idx >> 5, k = (idx & 31) << 1;
        int ua = u - 72;
        float a = 0.f, b = 0.f;
        if (ua >= 0 && ua < NRR) {
            a = rel[(size_t)ua * NDK + k] * LOG2E;
            b = rel[(size_t)ua * NDK + k + 1] * LOG2E;
        }
        g_relp[bp_off(k, u, 136)] = bf2(a, b);
    } else if (bid < 2384) {
        // zero padding rows 1000..1023
        int bh = bid - 2320;
        for (int f = threadIdx.x; f < 768; f += 256) {
            int m = 1000 + (f >> 5);
            int k = (f & 31) << 1;
            g_qp[bh * 32768 + a_off16(m, k, 4)] = 0;
            g_kp[bh * 32768 + bp_off(k, m, 64)] = 0;
            int k0v = 1000 + ((f >> 6) << 1);
            int dv = f & 63;
            g_vp[bh * 32768 + bp_off(k0v, dv, 4)] = 0;
        }
    } else {
        // layernorm: 2 rows per block
        int sub = threadIdx.x >> 7, t = threadIdx.x & 127;
        int row = ((bid - 2384) << 1) + sub;
        const float4 v = ((const float4*)(x + (size_t)row * ND))[t];
        float s = v.x + v.y + v.z + v.w;
#pragma unroll
        for (int o = 16; o; o >>= 1) s += __shfl_xor_sync(0xffffffffu, s, o);
        if ((t & 31) == 0) red[(sub << 2) + (t >> 5)] = s;
        __syncthreads();
        float mean = (red[sub << 2] + red[(sub << 2) + 1] + red[(sub << 2) + 2] +
                      red[(sub << 2) + 3]) * (1.0f / ND);
        __syncthreads();
        float a = v.x - mean, b = v.y - mean, c = v.z - mean, d = v.w - mean;
        float s2 = a * a + b * b + c * c + d * d;
#pragma unroll
        for (int o = 16; o; o >>= 1) s2 += __shfl_xor_sync(0xffffffffu, s2, o);
        if ((t & 31) == 0) red[(sub << 2) + (t >> 5)] = s2;
        __syncthreads();
        float var = (red[sub << 2] + red[(sub << 2) + 1] + red[(sub << 2) + 2] +
                     red[(sub << 2) + 3]) * (1.0f / ND);
        float inv = rsqrtf(var + 1e-5f);
        const float4 gg = ((const float4*)gamma)[t];
        const float4 bt = ((const float4*)beta)[t];
        int k0 = t << 2;
        g_xnp[a_off16(row, k0, 32)] = bf2(a * inv * gg.x + bt.x, b * inv * gg.y + bt.y);
        g_xnp[a_off16(row, k0 + 2, 32)] = bf2(c * inv * gg.z + bt.z, d * inv * gg.w + bt.w);
    }
}

// ---------------- streaming bf16 GEMM (no smem, no syncs) ---------------------
__global__ void __launch_bounds__(256) gemm2_kernel(
    const float* __restrict__ b0, const float* __restrict__ b1,
    const float* __restrict__ b2, const float* __restrict__ resid,
    float* __restrict__ Cf, int outproj) {
    const int tid = threadIdx.x, lane = tid & 31, warp = tid >> 5;
    const int wm = warp >> 2, wn = warp & 3, g = lane >> 2, tig = lane & 3;
    const int m0 = blockIdx.y * 64, n0 = blockIdx.x * 128;
    const int z = blockIdx.z;
    const int mode = outproj ? 1 : (z == 0 ? 0 : (z == 1 ? 2 : 3));
    const int widx = outproj ? 3 : z;
    const float* bias = outproj ? b0 : (z == 0 ? b0 : (z == 1 ? b1 : b2));
    const unsigned* Ap = outproj ? g_ctxp : g_xnp;
    const unsigned* Ab = Ap + (size_t)(((m0 + wm * 32) >> 4) * 32) * 128 + (lane << 2);
    const unsigned* Bb = g_wp + (size_t)widx * 131072 + (size_t)((n0 >> 3) + wn * 4) * 64 + (lane << 1);

    float4 acc[2][4] = {};
    uint4 a[2][2];
    uint2 b[2][4];
    a[0][0] = *(const uint4*)(Ab);
    a[0][1] = *(const uint4*)(Ab + 4096);
#pragma unroll
    for (int j = 0; j < 4; j++) b[0][j] = *(const uint2*)(Bb + j * 64);
#pragma unroll
    for (int kt = 0; kt < 32; kt++) {
        int cur = kt & 1, nxt = cur ^ 1;
        if (kt < 31) {
            a[nxt][0] = *(const uint4*)(Ab + (kt + 1) * 128);
            a[nxt][1] = *(const uint4*)(Ab + 4096 + (kt + 1) * 128);
#pragma unroll
            for (int j = 0; j < 4; j++)
                b[nxt][j] = *(const uint2*)(Bb + (size_t)(kt + 1) * 4096 + j * 64);
        }
#pragma unroll
        for (int j = 0; j < 4; j++) {
            mma16(acc[0][j], a[cur][0], b[cur][j]);
            mma16(acc[1][j], a[cur][1], b[cur][j]);
        }
    }

    const float KS = 0.125f * LOG2E;
#pragma unroll
    for (int i = 0; i < 2; i++)
#pragma unroll
        for (int j = 0; j < 4; j++) {
            int col = n0 + wn * 32 + j * 8 + (tig << 1);
            float2 bb = *(const float2*)&bias[col];
            float4 c = acc[i][j];
            float cx = c.x + bb.x, cy = c.y + bb.y;
            float cz = c.z + bb.x, cw = c.w + bb.y;
            int r0 = m0 + wm * 32 + i * 16 + g, r1 = r0 + 8;
            if (mode == 1) {
                size_t o0 = (size_t)r0 * ND + col, o1 = (size_t)r1 * ND + col;
                float2 rr0 = *(const float2*)&resid[o0];
                float2 rr1 = *(const float2*)&resid[o1];
                *(float2*)&Cf[o0] = make_float2(cx + rr0.x, cy + rr0.y);
                *(float2*)&Cf[o1] = make_float2(cz + rr1.x, cw + rr1.y);
            } else if (mode == 3) {
                // V: pair rows j, j+1 via shfl (lane^4 = row parity partner)
                float ox = __shfl_xor_sync(0xffffffffu, cx, 4);
                float oy = __shfl_xor_sync(0xffffffffu, cy, 4);
                float oz = __shfl_xor_sync(0xffffffffu, cz, 4);
                float ow = __shfl_xor_sync(0xffffffffu, cw, 4);
                if (!(g & 1)) {
                    int h = col >> 6, d = col & 63;
                    int b0i = r0 / NL, l0 = r0 - b0i * NL;
                    int b1i = r1 / NL, l1 = r1 - b1i * NL;
                    unsigned* vp0 = g_vp + (b0i * NH + h) * 32768;
                    unsigned* vp1 = g_vp + (b1i * NH + h) * 32768;
                    vp0[bp_off(l0, d, 4)] = bf2(cx, ox);
                    vp0[bp_off(l0, d + 1, 4)] = bf2(cy, oy);
                    vp1[bp_off(l1, d, 4)] = bf2(cz, oz);
                    vp1[bp_off(l1, d + 1, 4)] = bf2(cw, ow);
                }
            } else {
                int h = col >> 6, d = col & 63;
                int b0i = r0 / NL, l0 = r0 - b0i * NL;
                int b1i = r1 / NL, l1 = r1 - b1i * NL;
                int bh0 = b0i * NH + h, bh1 = b1i * NH + h;
                if (mode == 0) {
                    g_qp[bh0 * 32768 + a_off16(l0, d, 4)] = bf2(cx, cy);
                    g_qp[bh1 * 32768 + a_off16(l1, d, 4)] = bf2(cz, cw);
                } else {
                    g_kp[bh0 * 32768 + bp_off(d, l0, 64)] = bf2(cx * KS, cy * KS);
                    g_kp[bh1 * 32768 + bp_off(d, l1, 64)] = bf2(cz * KS, cw * KS);
                }
            }
        }
}

// ---------------- flash attention: warp-exclusive rows, pair-packed loads -----
#define S2STRIDE 19

__global__ void __launch_bounds__(128) attn_kernel() {
    __shared__ float S2all[4 * 128 * S2STRIDE];

    const int it = blockIdx.x, bh = blockIdx.y;
    const int bq = bh >> 3, h = bh & 7;
    const int i0 = it << 6;
    const int tid = threadIdx.x;
    const int lane = tid & 31, w = tid >> 5;
    const int g = lane >> 2, tig = lane & 3;
    float* S2w = S2all + w * 128 * S2STRIDE;

    const unsigned* qpb = g_qp + bh * 32768;
    const unsigned* kpb = g_kp + bh * 32768;
    const unsigned* vpb = g_vp + bh * 32768;

    uint4 qf[4];
#pragma unroll
    for (int kt = 0; kt < 4; kt++)
        qf[kt] = *(const uint4*)(qpb + (size_t)(((it << 2) + w) * 4 + kt) * 128 + (lane << 2));

    float rm0 = -1e30f, rm1 = -1e30f, rl0 = 0.f, rl1 = 0.f;
    float4 O[8] = {};

    // rel n8 offset: n = v + 1056 - i0 - 16w (even tile base by construction)
    const int nboff = (1056 - i0 - (w << 4)) >> 3;

    // warm the ring: v in [0, 80) -> 5 tile-pairs
#pragma unroll
    for (int p = 0; p < 5; p++) {
        int pair = p + (nboff >> 1);
        float4 a0 = make_float4(0.f, 0.f, 0.f, 0.f);
        float4 a1 = make_float4(0.f, 0.f, 0.f, 0.f);
#pragma unroll
        for (int kt = 0; kt < 4; kt++) {
            uint4 bb = *(const uint4*)(g_relp + (((size_t)kt * 136 + pair) << 7) + (lane << 2));
            mma16(a0, qf[kt], make_uint2(bb.x, bb.y));
            mma16(a1, qf[kt], make_uint2(bb.z, bb.w));
        }
        int sl = (p << 4) + (tig << 1);
        S2w[sl * S2STRIDE + g] = a0.x;
        S2w[(sl + 1) * S2STRIDE + g] = a0.y;
        S2w[sl * S2STRIDE + g + 8] = a0.z;
        S2w[(sl + 1) * S2STRIDE + g + 8] = a0.w;
        S2w[(sl + 8) * S2STRIDE + g] = a1.x;
        S2w[(sl + 9) * S2STRIDE + g] = a1.y;
        S2w[(sl + 8) * S2STRIDE + g + 8] = a1.z;
        S2w[(sl + 9) * S2STRIDE + g + 8] = a1.w;
    }
    __syncwarp();

    for (int jt = 0; jt < 16; jt++) {
        const int j0 = jt << 6;

        // S2: new band tiles v in [j0+16, j0+80) -> 4 tile-pairs into ring
#pragma unroll
        for (int p = 0; p < 4; p++) {
            int v8 = ((j0 + 16) >> 3) + (p << 1);
            int pair = (v8 + nboff) >> 1;
            float4 a0 = make_float4(0.f, 0.f, 0.f, 0.f);
            float4 a1 = make_float4(0.f, 0.f, 0.f, 0.f);
#pragma unroll
            for (int kt = 0; kt < 4; kt++) {
                uint4 bb = *(const uint4*)(g_relp + (((size_t)kt * 136 + pair) << 7) + (lane << 2));
                mma16(a0, qf[kt], make_uint2(bb.x, bb.y));
                mma16(a1, qf[kt], make_uint2(bb.z, bb.w));
            }
            int sl = ((j0 + 16 + (p << 4)) & 127) + (tig << 1);
            S2w[sl * S2STRIDE + g] = a0.x;
            S2w[(sl + 1) * S2STRIDE + g] = a0.y;
            S2w[sl * S2STRIDE + g + 8] = a0.z;
            S2w[(sl + 1) * S2STRIDE + g + 8] = a0.w;
            S2w[(sl + 8) * S2STRIDE + g] = a1.x;
            S2w[(sl + 9) * S2STRIDE + g] = a1.y;
            S2w[(sl + 8) * S2STRIDE + g + 8] = a1.z;
            S2w[(sl + 9) * S2STRIDE + g + 8] = a1.w;
        }
        __syncwarp();

        // S1 = Q @ K^T over 4 n8-tile pairs
        float4 s1[8] = {};
#pragma unroll
        for (int kt = 0; kt < 4; kt++) {
#pragma unroll
            for (int p = 0; p < 4; p++) {
                uint4 kk = *(const uint4*)(kpb +
                    (((size_t)(kt * 64 + (j0 >> 4) + p)) << 7) + (lane << 2));
                mma16(s1[2 * p], qf[kt], make_uint2(kk.x, kk.y));
                mma16(s1[2 * p + 1], qf[kt], make_uint2(kk.z, kk.w));
            }
        }

        // gather ring + mask + row max (warp-local)
        float m0 = -1e30f, m1 = -1e30f;
#pragma unroll
        for (int nt = 0; nt < 8; nt++) {
            int c = (nt << 3) + (tig << 1);
            int v0 = j0 + c - g + 15;
            int v1 = v0 - 8;
            s1[nt].x += S2w[(v0 & 127) * S2STRIDE + g];
            s1[nt].y += S2w[((v0 + 1) & 127) * S2STRIDE + g];
            s1[nt].z += S2w[(v1 & 127) * S2STRIDE + g + 8];
            s1[nt].w += S2w[((v1 + 1) & 127) * S2STRIDE + g + 8];
            if (j0 + c >= NL) { s1[nt].x = -1e30f; s1[nt].z = -1e30f; }
            if (j0 + c + 1 >= NL) { s1[nt].y = -1e30f; s1[nt].w = -1e30f; }
            m0 = fmaxf(m0, fmaxf(s1[nt].x, s1[nt].y));
            m1 = fmaxf(m1, fmaxf(s1[nt].z, s1[nt].w));
        }
        m0 = fmaxf(m0, __shfl_xor_sync(0xffffffffu, m0, 1));
        m0 = fmaxf(m0, __shfl_xor_sync(0xffffffffu, m0, 2));
        m1 = fmaxf(m1, __shfl_xor_sync(0xffffffffu, m1, 1));
        m1 = fmaxf(m1, __shfl_xor_sync(0xffffffffu, m1, 2));

        float mn0 = fmaxf(rm0, m0), mn1 = fmaxf(rm1, m1);
        float a0 = ex2f(rm0 - mn0), a1 = ex2f(rm1 - mn1);
        rm0 = mn0; rm1 = mn1;

        // exp -> P fragments in registers, row sums
        unsigned plo[8], phi[8];
        float s0 = 0.f, sh = 0.f;
#pragma unroll
        for (int nt = 0; nt < 8; nt++) {
            float e00 = ex2f(s1[nt].x - mn0), e01 = ex2f(s1[nt].y - mn0);
            float e10 = ex2f(s1[nt].z - mn1), e11 = ex2f(s1[nt].w - mn1);
            plo[nt] = bf2(e00, e01);
            phi[nt] = bf2(e10, e11);
            s0 += e00 + e01;
            sh += e10 + e11;
        }
        s0 += __shfl_xor_sync(0xffffffffu, s0, 1);
        s0 += __shfl_xor_sync(0xffffffffu, s0, 2);
        sh += __shfl_xor_sync(0xffffffffu, sh, 1);
        sh += __shfl_xor_sync(0xffffffffu, sh, 2);
        rl0 = rl0 * a0 + s0;
        rl1 = rl1 * a1 + sh;

        // O rescale, then O += P @ V (pair-packed V frags)
#pragma unroll
        for (int dnt = 0; dnt < 8; dnt++) {
            O[dnt].x *= a0; O[dnt].y *= a0;
            O[dnt].z *= a1; O[dnt].w *= a1;
        }
#pragma unroll
        for (int kt = 0; kt < 4; kt++) {
            uint4 pa = make_uint4(plo[2 * kt], phi[2 * kt], plo[2 * kt + 1], phi[2 * kt + 1]);
            const unsigned* vb2 = vpb + (((size_t)(((j0 >> 4) + kt) << 2)) << 7) + (lane << 2);
#pragma unroll
            for (int p = 0; p < 4; p++) {
                uint4 vv = *(const uint4*)(vb2 + (p << 7));
                mma16(O[2 * p], pa, make_uint2(vv.x, vv.y));
                mma16(O[2 * p + 1], pa, make_uint2(vv.z, vv.w));
            }
        }
        __syncwarp();
    }

    // normalize + write ctx as A-perm bf16
    float inv0 = 1.f / rl0, inv1 = 1.f / rl1;
    int r0g = i0 + (w << 4) + g, r1g = r0g + 8;
#pragma unroll
    for (int dnt = 0; dnt < 8; dnt++) {
        int col = (h << 6) + (dnt << 3) + (tig << 1);
        if (r0g < NL)
            g_ctxp[a_off16(bq * NL + r0g, col, 32)] = bf2(O[dnt].x * inv0, O[dnt].y * inv0);
        if (r1g < NL)
            g_ctxp[a_off16(bq * NL + r1g, col, 32)] = bf2(O[dnt].z * inv1, O[dnt].w * inv1);
    }
}

// ---------------- launch ------------------------------------------------------
extern "C" void kernel_launch(void* const* d_in, const int* in_sizes, int n_in,
                              void* d_out, int out_size) {
    const float* x     = (const float*)d_in[0];
    const float* Wq    = (const float*)d_in[1];
    const float* bq    = (const float*)d_in[2];
    const float* Wk    = (const float*)d_in[3];
    const float* bk    = (const float*)d_in[4];
    const float* Wv    = (const float*)d_in[5];
    const float* bv    = (const float*)d_in[6];
    const float* Wo    = (const float*)d_in[7];
    const float* bo    = (const float*)d_in[8];
    const float* rel   = (const float*)d_in[9];
    const float* gamma = (const float*)d_in[10];
    const float* beta  = (const float*)d_in[11];
    float* out = (float*)d_out;

    prep_kernel<<<6384, 256>>>(Wq, Wk, Wv, Wo, rel, x, gamma, beta);
    gemm2_kernel<<<dim3(4, 125, 3), 256>>>(bq, bk, bv, nullptr, nullptr, 0);  // QKV
    attn_kernel<<<dim3(16, NBH), 128>>>();
    gemm2_kernel<<<dim3(4, 125, 1), 256>>>(bo, nullptr, nullptr, x, out, 1);  // out-proj
}

// round 14
// speedup vs baseline: 3.2943x; 1.0493x over previous
#include <cuda_runtime.h>
#include <cuda_bf16.h>

#define NL 1000
#define ND 512
#define NH 8
#define NDK 64
#define NRR 1999
#define NBH 64
#define LOG2E 1.4426950408889634f

// ---------------- device scratch: pre-permuted bf16 fragment arrays -----------
__device__ unsigned g_xnp [500 * 32 * 128];   // xn  A-perm (8000 x 512)
__device__ unsigned g_ctxp[500 * 32 * 128];   // ctx A-perm (8000 x 512)
__device__ unsigned g_wp  [4 * 131072];       // W   B-perm (512k x 512n) x4
__device__ unsigned g_qp  [NBH * 32768];      // q per bh: A-perm (1024 x 64)
__device__ unsigned g_kp  [NBH * 32768];      // k per bh: pair-packed B (k=d, n=j)
__device__ unsigned g_vp  [NBH * 32768];      // v per bh: pair-packed B (k=j, n=d)
__device__ unsigned g_relp[4 * 136 * 128];    // rel*log2e pair-packed B (k=d, n=u+72)

// ---------------- helpers -----------------------------------------------------
__device__ __forceinline__ unsigned bf2(float lo, float hi) {
    unsigned r;
    asm("cvt.rn.bf16x2.f32 %0, %1, %2;" : "=r"(r) : "f"(hi), "f"(lo));
    return r;
}
__device__ __forceinline__ float ex2f(float x) {
    float r;
    asm("ex2.approx.ftz.f32 %0, %1;" : "=f"(r) : "f"(x));
    return r;
}
__device__ __forceinline__ void mma16(float4& d, uint4 a, uint2 b) {
    asm volatile(
        "mma.sync.aligned.m16n8k16.row.col.f32.bf16.bf16.f32 "
        "{%0,%1,%2,%3}, {%4,%5,%6,%7}, {%8,%9}, {%0,%1,%2,%3};\n"
        : "+f"(d.x), "+f"(d.y), "+f"(d.z), "+f"(d.w)
        : "r"(a.x), "r"(a.y), "r"(a.z), "r"(a.w), "r"(b.x), "r"(b.y));
}
// A tile 16x16 (u32 = bf16x2 over k)
__device__ __forceinline__ int a_off16(int m, int k, int nkt16) {
    return (((m >> 4) * nkt16 + (k >> 4)) << 7) +
           ((((m & 7) << 2) + ((k & 7) >> 1)) << 2) + ((m >> 3) & 1) + (((k >> 3) & 1) << 1);
}
// classic B tile 16x8 (for g_wp only)
__device__ __forceinline__ int b_off16(int k, int n, int nnt) {
    return (((k >> 4) * nnt + (n >> 3)) << 6) +
           ((((n & 7) << 2) + ((k & 7) >> 1)) << 1) + ((k >> 3) & 1);
}
// pair-packed B: two n8 tiles per 128-word block, per-lane 4 words
__device__ __forceinline__ int bp_off(int k, int n, int NP) {
    return (((k >> 4) * NP + (n >> 4)) << 7) +
           ((((n & 7) << 2) + ((k & 7) >> 1)) << 2) + (((n >> 3) & 1) << 1) + ((k >> 3) & 1);
}

// ---------------- fused preamble: wconv(4) + relconv + zfill + layernorm ------
__global__ void prep_kernel(const float* __restrict__ W0, const float* __restrict__ W1,
                            const float* __restrict__ W2, const float* __restrict__ W3,
                            const float* __restrict__ rel,
                            const float* __restrict__ x,
                            const float* __restrict__ gamma,
                            const float* __restrict__ beta) {
    __shared__ float red[8];
    int bid = blockIdx.x;
    if (bid < 2048) {
        int widx = bid >> 9;
        const float* W = (widx == 0) ? W0 : (widx == 1) ? W1 : (widx == 2) ? W2 : W3;
        int idx = ((bid & 511) << 8) + threadIdx.x;
        int n = idx >> 8, k = (idx & 255) << 1;
        g_wp[widx * 131072 + b_off16(k, n, 64)] =
            bf2(W[(size_t)n * ND + k], W[(size_t)n * ND + k + 1]);
    } else if (bid < 2320) {
        int idx = ((bid - 2048) << 8) + threadIdx.x;
        int u = idx >> 5, k = (idx & 31) << 1;
        int ua = u - 72;
        float a = 0.f, b = 0.f;
        if (ua >= 0 && ua < NRR) {
            a = rel[(size_t)ua * NDK + k] * LOG2E;
            b = rel[(size_t)ua * NDK + k + 1] * LOG2E;
        }
        g_relp[bp_off(k, u, 136)] = bf2(a, b);
    } else if (bid < 2384) {
        int bh = bid - 2320;
        for (int f = threadIdx.x; f < 768; f += 256) {
            int m = 1000 + (f >> 5);
            int k = (f & 31) << 1;
            g_qp[bh * 32768 + a_off16(m, k, 4)] = 0;
            g_kp[bh * 32768 + bp_off(k, m, 64)] = 0;
            int k0v = 1000 + ((f >> 6) << 1);
            int dv = f & 63;
            g_vp[bh * 32768 + bp_off(k0v, dv, 4)] = 0;
        }
    } else {
        int sub = threadIdx.x >> 7, t = threadIdx.x & 127;
        int row = ((bid - 2384) << 1) + sub;
        const float4 v = ((const float4*)(x + (size_t)row * ND))[t];
        float s = v.x + v.y + v.z + v.w;
#pragma unroll
        for (int o = 16; o; o >>= 1) s += __shfl_xor_sync(0xffffffffu, s, o);
        if ((t & 31) == 0) red[(sub << 2) + (t >> 5)] = s;
        __syncthreads();
        float mean = (red[sub << 2] + red[(sub << 2) + 1] + red[(sub << 2) + 2] +
                      red[(sub << 2) + 3]) * (1.0f / ND);
        __syncthreads();
        float a = v.x - mean, b = v.y - mean, c = v.z - mean, d = v.w - mean;
        float s2 = a * a + b * b + c * c + d * d;
#pragma unroll
        for (int o = 16; o; o >>= 1) s2 += __shfl_xor_sync(0xffffffffu, s2, o);
        if ((t & 31) == 0) red[(sub << 2) + (t >> 5)] = s2;
        __syncthreads();
        float var = (red[sub << 2] + red[(sub << 2) + 1] + red[(sub << 2) + 2] +
                     red[(sub << 2) + 3]) * (1.0f / ND);
        float inv = rsqrtf(var + 1e-5f);
        const float4 gg = ((const float4*)gamma)[t];
        const float4 bt = ((const float4*)beta)[t];
        int k0 = t << 2;
        g_xnp[a_off16(row, k0, 32)] = bf2(a * inv * gg.x + bt.x, b * inv * gg.y + bt.y);
        g_xnp[a_off16(row, k0 + 2, 32)] = bf2(c * inv * gg.z + bt.z, d * inv * gg.w + bt.w);
    }
}

// ---------------- streaming bf16 GEMM: 128 threads, 64x64 tile, high occ ------
__global__ void __launch_bounds__(128) gemm2_kernel(
    const float* __restrict__ b0, const float* __restrict__ b1,
    const float* __restrict__ b2, const float* __restrict__ resid,
    float* __restrict__ Cf, int outproj) {
    const int tid = threadIdx.x, lane = tid & 31, warp = tid >> 5;
    const int wm = warp >> 1, wn = warp & 1, g = lane >> 2, tig = lane & 3;
    const int m0 = blockIdx.y * 64, n0 = blockIdx.x * 64;
    const int z = blockIdx.z;
    const int mode = outproj ? 1 : (z == 0 ? 0 : (z == 1 ? 2 : 3));
    const int widx = outproj ? 3 : z;
    const float* bias = outproj ? b0 : (z == 0 ? b0 : (z == 1 ? b1 : b2));
    const unsigned* Ap = outproj ? g_ctxp : g_xnp;
    const unsigned* Ab = Ap + (size_t)(((m0 + wm * 32) >> 4) * 32) * 128 + (lane << 2);
    const unsigned* Bb = g_wp + (size_t)widx * 131072 + (size_t)((n0 >> 3) + wn * 4) * 64 + (lane << 1);

    float4 acc[2][4] = {};
    uint4 a[2][2];
    uint2 b[2][4];
    a[0][0] = *(const uint4*)(Ab);
    a[0][1] = *(const uint4*)(Ab + 4096);
#pragma unroll
    for (int j = 0; j < 4; j++) b[0][j] = *(const uint2*)(Bb + j * 64);
#pragma unroll
    for (int kt = 0; kt < 32; kt++) {
        int cur = kt & 1, nxt = cur ^ 1;
        if (kt < 31) {
            a[nxt][0] = *(const uint4*)(Ab + (kt + 1) * 128);
            a[nxt][1] = *(const uint4*)(Ab + 4096 + (kt + 1) * 128);
#pragma unroll
            for (int j = 0; j < 4; j++)
                b[nxt][j] = *(const uint2*)(Bb + (size_t)(kt + 1) * 4096 + j * 64);
        }
#pragma unroll
        for (int j = 0; j < 4; j++) {
            mma16(acc[0][j], a[cur][0], b[cur][j]);
            mma16(acc[1][j], a[cur][1], b[cur][j]);
        }
    }

    const float KS = 0.125f * LOG2E;
#pragma unroll
    for (int i = 0; i < 2; i++)
#pragma unroll
        for (int j = 0; j < 4; j++) {
            int col = n0 + wn * 32 + j * 8 + (tig << 1);
            float2 bb = *(const float2*)&bias[col];
            float4 c = acc[i][j];
            float cx = c.x + bb.x, cy = c.y + bb.y;
            float cz = c.z + bb.x, cw = c.w + bb.y;
            int r0 = m0 + wm * 32 + i * 16 + g, r1 = r0 + 8;
            if (mode == 1) {
                size_t o0 = (size_t)r0 * ND + col, o1 = (size_t)r1 * ND + col;
                float2 rr0 = *(const float2*)&resid[o0];
                float2 rr1 = *(const float2*)&resid[o1];
                *(float2*)&Cf[o0] = make_float2(cx + rr0.x, cy + rr0.y);
                *(float2*)&Cf[o1] = make_float2(cz + rr1.x, cw + rr1.y);
            } else if (mode == 3) {
                float ox = __shfl_xor_sync(0xffffffffu, cx, 4);
                float oy = __shfl_xor_sync(0xffffffffu, cy, 4);
                float oz = __shfl_xor_sync(0xffffffffu, cz, 4);
                float ow = __shfl_xor_sync(0xffffffffu, cw, 4);
                if (!(g & 1)) {
                    int h = col >> 6, d = col & 63;
                    int b0i = r0 / NL, l0 = r0 - b0i * NL;
                    int b1i = r1 / NL, l1 = r1 - b1i * NL;
                    unsigned* vp0 = g_vp + (b0i * NH + h) * 32768;
                    unsigned* vp1 = g_vp + (b1i * NH + h) * 32768;
                    vp0[bp_off(l0, d, 4)] = bf2(cx, ox);
                    vp0[bp_off(l0, d + 1, 4)] = bf2(cy, oy);
                    vp1[bp_off(l1, d, 4)] = bf2(cz, oz);
                    vp1[bp_off(l1, d + 1, 4)] = bf2(cw, ow);
                }
            } else {
                int h = col >> 6, d = col & 63;
                int b0i = r0 / NL, l0 = r0 - b0i * NL;
                int b1i = r1 / NL, l1 = r1 - b1i * NL;
                int bh0 = b0i * NH + h, bh1 = b1i * NH + h;
                if (mode == 0) {
                    g_qp[bh0 * 32768 + a_off16(l0, d, 4)] = bf2(cx, cy);
                    g_qp[bh1 * 32768 + a_off16(l1, d, 4)] = bf2(cz, cw);
                } else {
                    g_kp[bh0 * 32768 + bp_off(d, l0, 64)] = bf2(cx * KS, cy * KS);
                    g_kp[bh1 * 32768 + bp_off(d, l1, 64)] = bf2(cz * KS, cw * KS);
                }
            }
        }
}

// ---------------- flash attention: warp-exclusive rows, pair-packed loads -----
#define S2STRIDE 19

__global__ void __launch_bounds__(128) attn_kernel() {
    __shared__ float S2all[4 * 128 * S2STRIDE];

    const int it = blockIdx.x, bh = blockIdx.y;
    const int bq = bh >> 3, h = bh & 7;
    const int i0 = it << 6;
    const int tid = threadIdx.x;
    const int lane = tid & 31, w = tid >> 5;
    const int g = lane >> 2, tig = lane & 3;
    float* S2w = S2all + w * 128 * S2STRIDE;

    const unsigned* qpb = g_qp + bh * 32768;
    const unsigned* kpb = g_kp + bh * 32768;
    const unsigned* vpb = g_vp + bh * 32768;

    uint4 qf[4];
#pragma unroll
    for (int kt = 0; kt < 4; kt++)
        qf[kt] = *(const uint4*)(qpb + (size_t)(((it << 2) + w) * 4 + kt) * 128 + (lane << 2));

    float rm0 = -1e30f, rm1 = -1e30f, rl0 = 0.f, rl1 = 0.f;
    float4 O[8] = {};

    const int nboff = (1056 - i0 - (w << 4)) >> 3;

    // warm the ring: v in [0, 80) -> 5 tile-pairs
#pragma unroll
    for (int p = 0; p < 5; p++) {
        int pair = p + (nboff >> 1);
        float4 a0 = make_float4(0.f, 0.f, 0.f, 0.f);
        float4 a1 = make_float4(0.f, 0.f, 0.f, 0.f);
#pragma unroll
        for (int kt = 0; kt < 4; kt++) {
            uint4 bb = *(const uint4*)(g_relp + (((size_t)kt * 136 + pair) << 7) + (lane << 2));
            mma16(a0, qf[kt], make_uint2(bb.x, bb.y));
            mma16(a1, qf[kt], make_uint2(bb.z, bb.w));
        }
        int sl = (p << 4) + (tig << 1);
        S2w[sl * S2STRIDE + g] = a0.x;
        S2w[(sl + 1) * S2STRIDE + g] = a0.y;
        S2w[sl * S2STRIDE + g + 8] = a0.z;
        S2w[(sl + 1) * S2STRIDE + g + 8] = a0.w;
        S2w[(sl + 8) * S2STRIDE + g] = a1.x;
        S2w[(sl + 9) * S2STRIDE + g] = a1.y;
        S2w[(sl + 8) * S2STRIDE + g + 8] = a1.z;
        S2w[(sl + 9) * S2STRIDE + g + 8] = a1.w;
    }
    __syncwarp();

    for (int jt = 0; jt < 16; jt++) {
        const int j0 = jt << 6;

        // S2: new band tiles v in [j0+16, j0+80) -> 4 tile-pairs into ring
#pragma unroll
        for (int p = 0; p < 4; p++) {
            int v8 = ((j0 + 16) >> 3) + (p << 1);
            int pair = (v8 + nboff) >> 1;
            float4 a0 = make_float4(0.f, 0.f, 0.f, 0.f);
            float4 a1 = make_float4(0.f, 0.f, 0.f, 0.f);
#pragma unroll
            for (int kt = 0; kt < 4; kt++) {
                uint4 bb = *(const uint4*)(g_relp + (((size_t)kt * 136 + pair) << 7) + (lane << 2));
                mma16(a0, qf[kt], make_uint2(bb.x, bb.y));
                mma16(a1, qf[kt], make_uint2(bb.z, bb.w));
            }
            int sl = ((j0 + 16 + (p << 4)) & 127) + (tig << 1);
            S2w[sl * S2STRIDE + g] = a0.x;
            S2w[(sl + 1) * S2STRIDE + g] = a0.y;
            S2w[sl * S2STRIDE + g + 8] = a0.z;
            S2w[(sl + 1) * S2STRIDE + g + 8] = a0.w;
            S2w[(sl + 8) * S2STRIDE + g] = a1.x;
            S2w[(sl + 9) * S2STRIDE + g] = a1.y;
            S2w[(sl + 8) * S2STRIDE + g + 8] = a1.z;
            S2w[(sl + 9) * S2STRIDE + g + 8] = a1.w;
        }
        __syncwarp();

        // S1 = Q @ K^T over 4 n8-tile pairs
        float4 s1[8] = {};
#pragma unroll
        for (int kt = 0; kt < 4; kt++) {
#pragma unroll
            for (int p = 0; p < 4; p++) {
                uint4 kk = *(const uint4*)(kpb +
                    (((size_t)(kt * 64 + (j0 >> 4) + p)) << 7) + (lane << 2));
                mma16(s1[2 * p], qf[kt], make_uint2(kk.x, kk.y));
                mma16(s1[2 * p + 1], qf[kt], make_uint2(kk.z, kk.w));
            }
        }

        // gather ring + mask + row max (warp-local)
        float m0 = -1e30f, m1 = -1e30f;
#pragma unroll
        for (int nt = 0; nt < 8; nt++) {
            int c = (nt << 3) + (tig << 1);
            int v0 = j0 + c - g + 15;
            int v1 = v0 - 8;
            s1[nt].x += S2w[(v0 & 127) * S2STRIDE + g];
            s1[nt].y += S2w[((v0 + 1) & 127) * S2STRIDE + g];
            s1[nt].z += S2w[(v1 & 127) * S2STRIDE + g + 8];
            s1[nt].w += S2w[((v1 + 1) & 127) * S2STRIDE + g + 8];
            if (j0 + c >= NL) { s1[nt].x = -1e30f; s1[nt].z = -1e30f; }
            if (j0 + c + 1 >= NL) { s1[nt].y = -1e30f; s1[nt].w = -1e30f; }
            m0 = fmaxf(m0, fmaxf(s1[nt].x, s1[nt].y));
            m1 = fmaxf(m1, fmaxf(s1[nt].z, s1[nt].w));
        }
        m0 = fmaxf(m0, __shfl_xor_sync(0xffffffffu, m0, 1));
        m0 = fmaxf(m0, __shfl_xor_sync(0xffffffffu, m0, 2));
        m1 = fmaxf(m1, __shfl_xor_sync(0xffffffffu, m1, 1));
        m1 = fmaxf(m1, __shfl_xor_sync(0xffffffffu, m1, 2));

        // prefetch kt=0 V fragments — latency hides under the exp2/shfl work below
        uint4 vv0[4];
#pragma unroll
        for (int p = 0; p < 4; p++)
            vv0[p] = *(const uint4*)(vpb + (((size_t)((j0 >> 4) << 2)) << 7) +
                                     (p << 7) + (lane << 2));

        float mn0 = fmaxf(rm0, m0), mn1 = fmaxf(rm1, m1);
        float a0 = ex2f(rm0 - mn0), a1 = ex2f(rm1 - mn1);
        rm0 = mn0; rm1 = mn1;

        unsigned plo[8], phi[8];
        float s0 = 0.f, sh = 0.f;
#pragma unroll
        for (int nt = 0; nt < 8; nt++) {
            float e00 = ex2f(s1[nt].x - mn0), e01 = ex2f(s1[nt].y - mn0);
            float e10 = ex2f(s1[nt].z - mn1), e11 = ex2f(s1[nt].w - mn1);
            plo[nt] = bf2(e00, e01);
            phi[nt] = bf2(e10, e11);
            s0 += e00 + e01;
            sh += e10 + e11;
        }
        s0 += __shfl_xor_sync(0xffffffffu, s0, 1);
        s0 += __shfl_xor_sync(0xffffffffu, s0, 2);
        sh += __shfl_xor_sync(0xffffffffu, sh, 1);
        sh += __shfl_xor_sync(0xffffffffu, sh, 2);
        rl0 = rl0 * a0 + s0;
        rl1 = rl1 * a1 + sh;

        // O rescale, then O += P @ V
#pragma unroll
        for (int dnt = 0; dnt < 8; dnt++) {
            O[dnt].x *= a0; O[dnt].y *= a0;
            O[dnt].z *= a1; O[dnt].w *= a1;
        }
        {
            uint4 pa = make_uint4(plo[0], phi[0], plo[1], phi[1]);
#pragma unroll
            for (int p = 0; p < 4; p++) {
                mma16(O[2 * p], pa, make_uint2(vv0[p].x, vv0[p].y));
                mma16(O[2 * p + 1], pa, make_uint2(vv0[p].z, vv0[p].w));
            }
        }
#pragma unroll
        for (int kt = 1; kt < 4; kt++) {
            uint4 pa = make_uint4(plo[2 * kt], phi[2 * kt], plo[2 * kt + 1], phi[2 * kt + 1]);
            const unsigned* vb2 = vpb + (((size_t)(((j0 >> 4) + kt) << 2)) << 7) + (lane << 2);
#pragma unroll
            for (int p = 0; p < 4; p++) {
                uint4 vv = *(const uint4*)(vb2 + (p << 7));
                mma16(O[2 * p], pa, make_uint2(vv.x, vv.y));
                mma16(O[2 * p + 1], pa, make_uint2(vv.z, vv.w));
            }
        }
        __syncwarp();
    }

    // normalize + write ctx as A-perm bf16
    float inv0 = 1.f / rl0, inv1 = 1.f / rl1;
    int r0g = i0 + (w << 4) + g, r1g = r0g + 8;
#pragma unroll
    for (int dnt = 0; dnt < 8; dnt++) {
        int col = (h << 6) + (dnt << 3) + (tig << 1);
        if (r0g < NL)
            g_ctxp[a_off16(bq * NL + r0g, col, 32)] = bf2(O[dnt].x * inv0, O[dnt].y * inv0);
        if (r1g < NL)
            g_ctxp[a_off16(bq * NL + r1g, col, 32)] = bf2(O[dnt].z * inv1, O[dnt].w * inv1);
    }
}

// ---------------- launch ------------------------------------------------------
extern "C" void kernel_launch(void* const* d_in, const int* in_sizes, int n_in,
                              void* d_out, int out_size) {
    const float* x     = (const float*)d_in[0];
    const float* Wq    = (const float*)d_in[1];
    const float* bq    = (const float*)d_in[2];
    const float* Wk    = (const float*)d_in[3];
    const float* bk    = (const float*)d_in[4];
    const float* Wv    = (const float*)d_in[5];
    const float* bv    = (const float*)d_in[6];
    const float* Wo    = (const float*)d_in[7];
    const float* bo    = (const float*)d_in[8];
    const float* rel   = (const float*)d_in[9];
    const float* gamma = (const float*)d_in[10];
    const float* beta  = (const float*)d_in[11];
    float* out = (float*)d_out;

    prep_kernel<<<6384, 256>>>(Wq, Wk, Wv, Wo, rel, x, gamma, beta);
    gemm2_kernel<<<dim3(8, 125, 3), 128>>>(bq, bk, bv, nullptr, nullptr, 0);  // QKV
    attn_kernel<<<dim3(16, NBH), 128>>>();
    gemm2_kernel<<<dim3(8, 125, 1), 128>>>(bo, nullptr, nullptr, x, out, 1);  // out-proj
}